// round 14
// baseline (speedup 1.0000x reference)
#include <cuda_runtime.h>
#include <cuda_fp16.h>
#include <cuda_bf16.h>
#include <math.h>
#include <cstdint>

// Problem constants
#define BATCH 2
#define SEQ   2048
#define MROWS (BATCH*SEQ)       // 4096
#define DMODEL 1024
#define D3    (3*DMODEL)        // 3072
#define INNER (4*DMODEL)        // 4096
#define NHEAD 16
#define HDIM  64

// ---------------- scratch (device globals; no allocations allowed) ----------
__device__ __half g_hh  [MROWS*DMODEL];   // LN output (fp16)
__device__ __half g_qkvh[MROWS*D3];       // QKV projection (fp16)
__device__ __half g_oh  [MROWS*DMODEL];   // attention output (fp16)
__device__ float  g_x1  [MROWS*DMODEL];   // residual after attention (fp32)
__device__ __half g_fc1h[MROWS*INNER];    // FC1+GELU output (fp16)
__device__ __half g_wTh [12*1024*1024];   // transposed fp16 weights

// ---------------- helpers ----------------
__device__ __forceinline__ uint32_t smem_u32(const void* p) {
    uint32_t a;
    asm("{ .reg .u64 t; cvta.to.shared.u64 t, %1; cvt.u32.u64 %0, t; }" : "=r"(a) : "l"(p));
    return a;
}
#define SW64(x)  ((x) ^ (((x) >> 3) & 0x30))
#define SW128(x) ((x) ^ (((x) >> 3) & 0x70))
#define CP16(sa, ga) \
    asm volatile("cp.async.cg.shared.global [%0], [%1], 16;" :: "r"(sa), "l"(ga) : "memory")

__device__ __forceinline__ void ldsm4(uint32_t* r, uint32_t a) {
    asm volatile("ldmatrix.sync.aligned.m8n8.x4.shared.b16 {%0,%1,%2,%3}, [%4];"
        : "=r"(r[0]), "=r"(r[1]), "=r"(r[2]), "=r"(r[3]) : "r"(a));
}
__device__ __forceinline__ void ldsm4t(uint32_t* r, uint32_t a) {
    asm volatile("ldmatrix.sync.aligned.m8n8.x4.trans.shared.b16 {%0,%1,%2,%3}, [%4];"
        : "=r"(r[0]), "=r"(r[1]), "=r"(r[2]), "=r"(r[3]) : "r"(a));
}
__device__ __forceinline__ void mma16(float* d, const uint32_t* a, const uint32_t* b) {
    asm volatile("mma.sync.aligned.m16n8k16.row.col.f32.f16.f16.f32 "
        "{%0,%1,%2,%3}, {%4,%5,%6,%7}, {%8,%9}, {%0,%1,%2,%3};"
        : "+f"(d[0]), "+f"(d[1]), "+f"(d[2]), "+f"(d[3])
        : "r"(a[0]), "r"(a[1]), "r"(a[2]), "r"(a[3]), "r"(b[0]), "r"(b[1]));
}

// ---------------- transpose to fp16 (vectorized, conflict-free) -------------
// 32x32 tile, 256 threads. Load: float4 per thread (128B coalesced rows).
// Store: 4 halves (uint2) per thread, 64B coalesced per dst row.
// Smem bank check (33-float stride): read bank = (seg*4 + oc + j) mod 32 with
// oc in 0..3, seg in 0..7 per warp -> all 32 banks distinct per j.
__global__ __launch_bounds__(256) void transpose_kernel(
    const float* __restrict__ src, __half* __restrict__ dst, int R, int C)
{
    __shared__ float tile[32][33];
    const int c0 = blockIdx.x * 32, r0 = blockIdx.y * 32;
    const int tid = threadIdx.x;

    {
        const int row = tid >> 3, cg = tid & 7;
        const float4 v = *(const float4*)(src + (size_t)(r0 + row) * C + c0 + cg * 4);
        tile[row][cg * 4 + 0] = v.x;
        tile[row][cg * 4 + 1] = v.y;
        tile[row][cg * 4 + 2] = v.z;
        tile[row][cg * 4 + 3] = v.w;
    }
    __syncthreads();
    {
        const int oc = tid >> 3, seg = tid & 7;
        __half2 h01 = __floats2half2_rn(tile[seg * 4 + 0][oc], tile[seg * 4 + 1][oc]);
        __half2 h23 = __floats2half2_rn(tile[seg * 4 + 2][oc], tile[seg * 4 + 3][oc]);
        uint2 pk;
        pk.x = *(uint32_t*)&h01;
        pk.y = *(uint32_t*)&h23;
        *(uint2*)(dst + (size_t)(c0 + oc) * R + r0 + seg * 4) = pk;
    }
}

// ---------------- fp16 tensor-core GEMM (R9/R10 locked optimum) -------------
// CTA tile 128x128, 4 warps (2x2) of 64x64, K-chunk = 32 halves (64B rows,
// SW64), 4-stage cp.async pipeline, 128 threads, 2 CTAs/SM.
#define GS_ABYTES 8192
#define GS_STAGE  16384
#define GEMM_SMEM (4 * GS_STAGE)   // 65536

template<int EPI, typename CT>
__global__ __launch_bounds__(128, 2) void hgemm_tc(
    const __half* __restrict__ A, const __half* __restrict__ Bt,
    const float* __restrict__ bias, const float* __restrict__ res,
    CT* __restrict__ C, int M, int N, int K)
{
    extern __shared__ char smem[];
    const uint32_t sb = smem_u32(smem);
    const int tid = threadIdx.x, lane = tid & 31, wid = tid >> 5;
    const int warp_m = wid >> 1, warp_n = wid & 1;
    const int m0 = blockIdx.y * 128, n0 = blockIdx.x * 128;
    const int mb = warp_m * 64, nb = warp_n * 64;

    const int u = lane >> 3, ur = lane & 7;
    uint32_t aoff[4], boff[4];
#pragma unroll
    for (int i = 0; i < 4; i++)
        aoff[i] = (uint32_t)(mb + i * 16 + (u & 1) * 8 + ur) * 64 + (u >> 1) * 16;
#pragma unroll
    for (int p = 0; p < 4; p++)
        boff[p] = (uint32_t)(nb + p * 16 + (u >> 1) * 8 + ur) * 64 + (u & 1) * 16;

    float acc[4][8][4];
#pragma unroll
    for (int i = 0; i < 4; i++)
#pragma unroll
        for (int j = 0; j < 8; j++)
#pragma unroll
            for (int q = 0; q < 4; q++) acc[i][j][q] = 0.f;

    const int nk = K >> 5;

#define H_ISSUE(t)                                                             \
    do {                                                                       \
        const uint32_t sa_ = sb + ((t) & 3) * GS_STAGE;                        \
        const uint32_t sbB_ = sa_ + GS_ABYTES;                                 \
        _Pragma("unroll")                                                      \
        for (int i_ = 0; i_ < 4; i_++) {                                       \
            const int idx_ = tid + 128 * i_;                                   \
            const int r_ = idx_ >> 2, c_ = idx_ & 3;                           \
            const uint32_t so_ = SW64((uint32_t)r_ * 64 + c_ * 16);            \
            CP16(sa_ + so_, A + (size_t)(m0 + r_) * K + (t) * 32 + c_ * 8);    \
            CP16(sbB_ + so_, Bt + (size_t)(n0 + r_) * K + (t) * 32 + c_ * 8);  \
        }                                                                      \
        asm volatile("cp.async.commit_group;" ::: "memory");                   \
    } while (0)

    H_ISSUE(0); H_ISSUE(1); H_ISSUE(2);

    for (int t = 0; t < nk; t++) {
        const int rem = nk - 1 - t;
        if (rem >= 2)       asm volatile("cp.async.wait_group 2;" ::: "memory");
        else if (rem == 1)  asm volatile("cp.async.wait_group 1;" ::: "memory");
        else                asm volatile("cp.async.wait_group 0;" ::: "memory");
        __syncthreads();

        if (t + 3 < nk) H_ISSUE(t + 3);

        const uint32_t sa = sb + (t & 3) * GS_STAGE;
        const uint32_t sbB = sa + GS_ABYTES;
#pragma unroll
        for (int s = 0; s < 2; s++) {
            uint32_t af[4][4], bf[8][2];
#pragma unroll
            for (int i = 0; i < 4; i++)
                ldsm4(af[i], sa + SW64(aoff[i] + s * 32));
#pragma unroll
            for (int p = 0; p < 4; p++) {
                uint32_t r4[4];
                ldsm4(r4, sbB + SW64(boff[p] + s * 32));
                bf[2 * p][0] = r4[0]; bf[2 * p][1] = r4[1];
                bf[2 * p + 1][0] = r4[2]; bf[2 * p + 1][1] = r4[3];
            }
#pragma unroll
            for (int i = 0; i < 4; i++)
#pragma unroll
                for (int j = 0; j < 8; j++) mma16(acc[i][j], af[i], bf[j]);
        }
        __syncthreads();
    }
#undef H_ISSUE

    // ---- epilogue ----
    const int r0 = m0 + mb + (lane >> 2);
    const int c0 = n0 + nb + (lane & 3) * 2;
#pragma unroll
    for (int i = 0; i < 4; i++) {
#pragma unroll
        for (int j = 0; j < 8; j++) {
            const int col = c0 + j * 8;
            const float bx = bias[col], by = bias[col + 1];
#pragma unroll
            for (int hh = 0; hh < 2; hh++) {
                const int row = r0 + i * 16 + hh * 8;
                float vx = acc[i][j][hh * 2 + 0] + bx;
                float vy = acc[i][j][hh * 2 + 1] + by;
                if (EPI == 1) {
                    const float2 rr = *(const float2*)(res + (size_t)row * N + col);
                    vx += rr.x; vy += rr.y;
                }
                if (EPI == 2) {
                    vx = 0.5f * vx * (1.f + erff(vx * 0.70710678118654752f));
                    vy = 0.5f * vy * (1.f + erff(vy * 0.70710678118654752f));
                }
                CT* cp = C + (size_t)row * N + col;
                if (sizeof(CT) == 2) {
                    *(__half2*)cp = __floats2half2_rn(vx, vy);
                } else {
                    float2 v; v.x = vx; v.y = vy;
                    *(float2*)cp = v;
                }
            }
        }
    }
}

// ---------------- LayerNorm (fp16 output, fully vectorized) -----------------
__global__ __launch_bounds__(256) void ln_kernel(
    const float* __restrict__ x, const float* __restrict__ g,
    const float* __restrict__ b, __half* __restrict__ out)
{
    __shared__ float red[16];
    const size_t row = blockIdx.x;
    const int tid = threadIdx.x;

    const float4 v = ((const float4*)(x + row * DMODEL))[tid];
    float s1 = v.x + v.y + v.z + v.w;
    float s2 = v.x * v.x + v.y * v.y + v.z * v.z + v.w * v.w;
#pragma unroll
    for (int o = 16; o; o >>= 1) {
        s1 += __shfl_xor_sync(0xffffffffu, s1, o);
        s2 += __shfl_xor_sync(0xffffffffu, s2, o);
    }
    if ((tid & 31) == 0) { red[tid >> 5] = s1; red[8 + (tid >> 5)] = s2; }
    __syncthreads();
    if (tid < 32) {
        float a = (tid < 8) ? red[tid] : 0.f;
        float c = (tid < 8) ? red[8 + tid] : 0.f;
#pragma unroll
        for (int o = 4; o; o >>= 1) {
            a += __shfl_xor_sync(0xffffffffu, a, o);
            c += __shfl_xor_sync(0xffffffffu, c, o);
        }
        if (tid == 0) { red[0] = a; red[8] = c; }
    }
    __syncthreads();
    const float mu  = red[0] * (1.f / DMODEL);
    const float var = red[8] * (1.f / DMODEL) - mu * mu;
    const float r   = rsqrtf(var + 1e-5f);

    const float4 gg = ((const float4*)g)[tid];
    const float4 bb = ((const float4*)b)[tid];
    __half2 h01 = __floats2half2_rn((v.x - mu) * r * gg.x + bb.x,
                                    (v.y - mu) * r * gg.y + bb.y);
    __half2 h23 = __floats2half2_rn((v.z - mu) * r * gg.z + bb.z,
                                    (v.w - mu) * r * gg.w + bb.w);
    uint2 pk;
    pk.x = *(uint32_t*)&h01;
    pk.y = *(uint32_t*)&h23;
    *(uint2*)(out + row * DMODEL + tid * 4) = pk;
}

// ---------------- fp16 tensor-core flash attention (3-stage K/V) ------------
#define AT_KV_STAGE 16384
#define ATT_SMEM (16384 + 3 * AT_KV_STAGE)   // 65536

__global__ __launch_bounds__(256) void attn_h_kernel(
    const __half* __restrict__ qkv, __half* __restrict__ o)
{
    extern __shared__ char sm[];
    const uint32_t uQ = smem_u32(sm);
    const uint32_t uKV = uQ + 16384;

    const int tid = threadIdx.x, lane = tid & 31, w = tid >> 5;
    const int bh = blockIdx.y;
    const int b = bh >> 4, h = bh & 15;
    const int qb = (int)gridDim.x - 1 - (int)blockIdx.x;
    const int q0 = qb * 128;
    const size_t bL = (size_t)b * SEQ;

    const int u = lane >> 3, ur = lane & 7;
    const uint32_t aoff = (uint32_t)(w * 16 + (u & 1) * 8 + ur) * 128 + (u >> 1) * 16;
    uint32_t boffK[4];
#pragma unroll
    for (int p = 0; p < 4; p++)
        boffK[p] = (uint32_t)(p * 16 + (u >> 1) * 8 + ur) * 128 + (u & 1) * 16;
    uint32_t boffV[4];
#pragma unroll
    for (int p = 0; p < 4; p++)
        boffV[p] = (uint32_t)((u & 1) * 8 + ur) * 128 + p * 32 + (u >> 1) * 16;

#define A_ISSUE(kb)                                                            \
    do {                                                                       \
        const uint32_t uS_ = uKV + ((kb) % 3) * AT_KV_STAGE;                   \
        _Pragma("unroll")                                                      \
        for (int i_ = 0; i_ < 2; i_++) {                                       \
            const int idx_ = tid + 256 * i_;                                   \
            const int r_ = idx_ >> 3, c_ = idx_ & 7;                           \
            const uint32_t so_ = SW128((uint32_t)r_ * 128 + c_ * 16);          \
            const __half* kp_ = qkv + (bL + (kb) * 64 + r_) * D3 + DMODEL      \
                                + h * HDIM + c_ * 8;                           \
            CP16(uS_ + so_, kp_);                                              \
            CP16(uS_ + 8192 + so_, kp_ + DMODEL);                              \
        }                                                                      \
        asm volatile("cp.async.commit_group;" ::: "memory");                   \
    } while (0)

    const int nkb = 2 * qb + 2;

    A_ISSUE(0);
    {
#pragma unroll
        for (int i = 0; i < 4; i++) {
            const int idx = tid + 256 * i;
            const int r = idx >> 3, c = idx & 7;
            CP16(uQ + SW128((uint32_t)r * 128 + c * 16),
                 qkv + (bL + q0 + r) * D3 + h * HDIM + c * 8);
        }
        asm volatile("cp.async.commit_group;" ::: "memory");
    }
    if (nkb > 1) A_ISSUE(1);
    if (nkb > 1) asm volatile("cp.async.wait_group 1;" ::: "memory");
    else         asm volatile("cp.async.wait_group 0;" ::: "memory");
    __syncthreads();

    uint32_t qf[4][4];
#pragma unroll
    for (int s = 0; s < 4; s++) ldsm4(qf[s], uQ + SW128(aoff + s * 32));

    float oa[8][4];
#pragma unroll
    for (int n = 0; n < 8; n++)
#pragma unroll
        for (int q = 0; q < 4; q++) oa[n][q] = 0.f;
    float m_lo = -1e30f, m_hi = -1e30f, l_lo = 0.f, l_hi = 0.f;

    const int grow_lo = q0 + w * 16 + (lane >> 2);
    const int grow_hi = grow_lo + 8;

    for (int kb = 0; kb < nkb; kb++) {
        if (kb + 2 < nkb) A_ISSUE(kb + 2);
        const int rem = nkb - 1 - kb;
        if (rem >= 2)      asm volatile("cp.async.wait_group 2;" ::: "memory");
        else if (rem == 1) asm volatile("cp.async.wait_group 1;" ::: "memory");
        else               asm volatile("cp.async.wait_group 0;" ::: "memory");
        __syncthreads();

        const uint32_t uK = uKV + (kb % 3) * AT_KV_STAGE;
        const uint32_t uV = uK + 8192;

        float sc[8][4];
#pragma unroll
        for (int n = 0; n < 8; n++)
#pragma unroll
            for (int q = 0; q < 4; q++) sc[n][q] = 0.f;
#pragma unroll
        for (int s = 0; s < 4; s++) {
            uint32_t bf[8][2];
#pragma unroll
            for (int p = 0; p < 4; p++) {
                uint32_t r4[4];
                ldsm4(r4, uK + SW128(boffK[p] + s * 32));
                bf[2 * p][0] = r4[0]; bf[2 * p][1] = r4[1];
                bf[2 * p + 1][0] = r4[2]; bf[2 * p + 1][1] = r4[3];
            }
#pragma unroll
            for (int n = 0; n < 8; n++) mma16(sc[n], qf[s], bf[n]);
        }

        const bool need_mask = (kb >= 2 * qb);
        const int c0g = kb * 64 + (lane & 3) * 2;
#pragma unroll
        for (int n = 0; n < 8; n++) {
            const int col0 = c0g + n * 8, col1 = col0 + 1;
            float s0 = sc[n][0] * 0.125f, s1 = sc[n][1] * 0.125f;
            float s2 = sc[n][2] * 0.125f, s3 = sc[n][3] * 0.125f;
            if (need_mask) {
                if (col0 > grow_lo) s0 = -1e30f;
                if (col1 > grow_lo) s1 = -1e30f;
                if (col0 > grow_hi) s2 = -1e30f;
                if (col1 > grow_hi) s3 = -1e30f;
            }
            sc[n][0] = s0; sc[n][1] = s1; sc[n][2] = s2; sc[n][3] = s3;
        }

        float bm_lo = -1e30f, bm_hi = -1e30f;
#pragma unroll
        for (int n = 0; n < 8; n++) {
            bm_lo = fmaxf(bm_lo, fmaxf(sc[n][0], sc[n][1]));
            bm_hi = fmaxf(bm_hi, fmaxf(sc[n][2], sc[n][3]));
        }
        bm_lo = fmaxf(bm_lo, __shfl_xor_sync(0xffffffffu, bm_lo, 1));
        bm_lo = fmaxf(bm_lo, __shfl_xor_sync(0xffffffffu, bm_lo, 2));
        bm_hi = fmaxf(bm_hi, __shfl_xor_sync(0xffffffffu, bm_hi, 1));
        bm_hi = fmaxf(bm_hi, __shfl_xor_sync(0xffffffffu, bm_hi, 2));
        const float mn_lo = fmaxf(m_lo, bm_lo);
        const float mn_hi = fmaxf(m_hi, bm_hi);
        const float f_lo = __expf(m_lo - mn_lo);
        const float f_hi = __expf(m_hi - mn_hi);
        m_lo = mn_lo; m_hi = mn_hi;

        float ps_lo = 0.f, ps_hi = 0.f;
#pragma unroll
        for (int n = 0; n < 8; n++) {
            sc[n][0] = __expf(sc[n][0] - mn_lo);
            sc[n][1] = __expf(sc[n][1] - mn_lo);
            sc[n][2] = __expf(sc[n][2] - mn_hi);
            sc[n][3] = __expf(sc[n][3] - mn_hi);
            ps_lo += sc[n][0] + sc[n][1];
            ps_hi += sc[n][2] + sc[n][3];
        }
        ps_lo += __shfl_xor_sync(0xffffffffu, ps_lo, 1);
        ps_lo += __shfl_xor_sync(0xffffffffu, ps_lo, 2);
        ps_hi += __shfl_xor_sync(0xffffffffu, ps_hi, 1);
        ps_hi += __shfl_xor_sync(0xffffffffu, ps_hi, 2);
        l_lo = l_lo * f_lo + ps_lo;
        l_hi = l_hi * f_hi + ps_hi;

#pragma unroll
        for (int n = 0; n < 8; n++) {
            oa[n][0] *= f_lo; oa[n][1] *= f_lo;
            oa[n][2] *= f_hi; oa[n][3] *= f_hi;
        }

        {
            const uint32_t plo = (uint32_t)(w * 16 + (lane >> 2)) * 128 + (lane & 3) * 4;
            const uint32_t phi = plo + 8 * 128;
#pragma unroll
            for (int n = 0; n < 8; n++) {
                *(__half2*)(sm + SW128(plo + n * 16)) = __floats2half2_rn(sc[n][0], sc[n][1]);
                *(__half2*)(sm + SW128(phi + n * 16)) = __floats2half2_rn(sc[n][2], sc[n][3]);
            }
        }
        __syncwarp();

#pragma unroll
        for (int s = 0; s < 4; s++) {
            uint32_t ap[4];
            ldsm4(ap, uQ + SW128(aoff + s * 32));
#pragma unroll
            for (int p = 0; p < 4; p++) {
                uint32_t r4[4];
                ldsm4t(r4, uV + SW128(boffV[p] + s * 16 * 128));
                uint32_t b0[2] = { r4[0], r4[1] };
                uint32_t b1[2] = { r4[2], r4[3] };
                mma16(oa[2 * p], ap, b0);
                mma16(oa[2 * p + 1], ap, b1);
            }
        }
        __syncthreads();
    }
#undef A_ISSUE

    const float inv_lo = 1.f / l_lo, inv_hi = 1.f / l_hi;
    __half* orow_lo = o + (bL + grow_lo) * DMODEL + h * HDIM + (lane & 3) * 2;
    __half* orow_hi = o + (bL + grow_hi) * DMODEL + h * HDIM + (lane & 3) * 2;
#pragma unroll
    for (int n = 0; n < 8; n++) {
        *(__half2*)(orow_lo + n * 8) = __floats2half2_rn(oa[n][0] * inv_lo, oa[n][1] * inv_lo);
        *(__half2*)(orow_hi + n * 8) = __floats2half2_rn(oa[n][2] * inv_hi, oa[n][3] * inv_hi);
    }
}

// ---------------- launcher ----------------
extern "C" void kernel_launch(void* const* d_in, const int* in_sizes, int n_in,
                              void* d_out, int out_size)
{
    const float* x     = (const float*)d_in[0];
    const float* w_qkv = (const float*)d_in[1];
    const float* b_qkv = (const float*)d_in[2];
    const float* w_out = (const float*)d_in[3];
    const float* b_out = (const float*)d_in[4];
    const float* w_fc1 = (const float*)d_in[5];
    const float* b_fc1 = (const float*)d_in[6];
    const float* w_fc2 = (const float*)d_in[7];
    const float* b_fc2 = (const float*)d_in[8];
    const float* ln1_g = (const float*)d_in[9];
    const float* ln1_b = (const float*)d_in[10];
    const float* ln2_g = (const float*)d_in[11];
    const float* ln2_b = (const float*)d_in[12];
    float* out = (float*)d_out;

    __half *h, *qkv, *o, *fc1, *wT;
    float *x1;
    cudaGetSymbolAddress((void**)&h,   g_hh);
    cudaGetSymbolAddress((void**)&qkv, g_qkvh);
    cudaGetSymbolAddress((void**)&o,   g_oh);
    cudaGetSymbolAddress((void**)&x1,  g_x1);
    cudaGetSymbolAddress((void**)&fc1, g_fc1h);
    cudaGetSymbolAddress((void**)&wT,  g_wTh);

    __half* wqkvT = wT;                       // [3072,1024]
    __half* woutT = wqkvT + 3072 * 1024;      // [1024,1024]
    __half* wfc1T = woutT + 1024 * 1024;      // [4096,1024]
    __half* wfc2T = wfc1T + 4096 * 1024;      // [1024,4096]

    cudaFuncSetAttribute((const void*)hgemm_tc<0, __half>, cudaFuncAttributeMaxDynamicSharedMemorySize, GEMM_SMEM);
    cudaFuncSetAttribute((const void*)hgemm_tc<1, float>,  cudaFuncAttributeMaxDynamicSharedMemorySize, GEMM_SMEM);
    cudaFuncSetAttribute((const void*)hgemm_tc<2, __half>, cudaFuncAttributeMaxDynamicSharedMemorySize, GEMM_SMEM);
    cudaFuncSetAttribute(attn_h_kernel, cudaFuncAttributeMaxDynamicSharedMemorySize, ATT_SMEM);

    // 0) transpose weights (fp16, vectorized)
    transpose_kernel<<<dim3(D3 / 32,    DMODEL / 32), 256>>>(w_qkv, wqkvT, DMODEL, D3);
    transpose_kernel<<<dim3(DMODEL / 32, DMODEL / 32), 256>>>(w_out, woutT, DMODEL, DMODEL);
    transpose_kernel<<<dim3(INNER / 32,  DMODEL / 32), 256>>>(w_fc1, wfc1T, DMODEL, INNER);
    transpose_kernel<<<dim3(DMODEL / 32, INNER / 32), 256>>>(w_fc2, wfc2T, INNER, DMODEL);

    // 1) LN1 (fp16 out)
    ln_kernel<<<MROWS, 256>>>(x, ln1_g, ln1_b, h);

    // 2) QKV projection (fp16 out)
    hgemm_tc<0, __half><<<dim3(D3 / 128, MROWS / 128), 128, GEMM_SMEM>>>(
        h, wqkvT, b_qkv, nullptr, qkv, MROWS, D3, DMODEL);

    // 3) causal attention (fp16 tensor cores, 3-stage K/V)
    attn_h_kernel<<<dim3(SEQ / 128, BATCH * NHEAD), 256, ATT_SMEM>>>(qkv, o);

    // 4) out projection + residual (fp32 out)
    hgemm_tc<1, float><<<dim3(DMODEL / 128, MROWS / 128), 128, GEMM_SMEM>>>(
        o, woutT, b_out, x, x1, MROWS, DMODEL, DMODEL);

    // 5) LN2 (fp16 out)
    ln_kernel<<<MROWS, 256>>>(x1, ln2_g, ln2_b, h);

    // 6) FC1 + exact GELU (fp16 out)
    hgemm_tc<2, __half><<<dim3(INNER / 128, MROWS / 128), 128, GEMM_SMEM>>>(
        h, wfc1T, b_fc1, nullptr, fc1, MROWS, INNER, DMODEL);

    // 7) FC2 + residual -> out (fp32)
    hgemm_tc<1, float><<<dim3(DMODEL / 128, MROWS / 128), 128, GEMM_SMEM>>>(
        fc1, wfc2T, b_fc2, x1, out, MROWS, DMODEL, INNER);
}

// round 15
// speedup vs baseline: 1.0125x; 1.0125x over previous
#include <cuda_runtime.h>
#include <cuda_fp16.h>
#include <cuda_bf16.h>
#include <math.h>
#include <cstdint>

// Problem constants
#define BATCH 2
#define SEQ   2048
#define MROWS (BATCH*SEQ)       // 4096
#define DMODEL 1024
#define D3    (3*DMODEL)        // 3072
#define INNER (4*DMODEL)        // 4096
#define NHEAD 16
#define HDIM  64

// ---------------- scratch (device globals; no allocations allowed) ----------
__device__ __half g_hh  [MROWS*DMODEL];   // LN output (fp16)
__device__ __half g_qkvh[MROWS*D3];       // QKV projection (fp16)
__device__ __half g_oh  [MROWS*DMODEL];   // attention output (fp16)
__device__ __half g_x1h [MROWS*DMODEL];   // residual after attention (fp16)
__device__ __half g_fc1h[MROWS*INNER];    // FC1+GELU output (fp16)
__device__ __half g_wTh [12*1024*1024];   // transposed fp16 weights

// ---------------- helpers ----------------
__device__ __forceinline__ uint32_t smem_u32(const void* p) {
    uint32_t a;
    asm("{ .reg .u64 t; cvta.to.shared.u64 t, %1; cvt.u32.u64 %0, t; }" : "=r"(a) : "l"(p));
    return a;
}
#define SW64(x)  ((x) ^ (((x) >> 3) & 0x30))
#define SW128(x) ((x) ^ (((x) >> 3) & 0x70))
#define CP16(sa, ga) \
    asm volatile("cp.async.cg.shared.global [%0], [%1], 16;" :: "r"(sa), "l"(ga) : "memory")

__device__ __forceinline__ void ldsm4(uint32_t* r, uint32_t a) {
    asm volatile("ldmatrix.sync.aligned.m8n8.x4.shared.b16 {%0,%1,%2,%3}, [%4];"
        : "=r"(r[0]), "=r"(r[1]), "=r"(r[2]), "=r"(r[3]) : "r"(a));
}
__device__ __forceinline__ void ldsm4t(uint32_t* r, uint32_t a) {
    asm volatile("ldmatrix.sync.aligned.m8n8.x4.trans.shared.b16 {%0,%1,%2,%3}, [%4];"
        : "=r"(r[0]), "=r"(r[1]), "=r"(r[2]), "=r"(r[3]) : "r"(a));
}
__device__ __forceinline__ void mma16(float* d, const uint32_t* a, const uint32_t* b) {
    asm volatile("mma.sync.aligned.m16n8k16.row.col.f32.f16.f16.f32 "
        "{%0,%1,%2,%3}, {%4,%5,%6,%7}, {%8,%9}, {%0,%1,%2,%3};"
        : "+f"(d[0]), "+f"(d[1]), "+f"(d[2]), "+f"(d[3])
        : "r"(a[0]), "r"(a[1]), "r"(a[2]), "r"(a[3]), "r"(b[0]), "r"(b[1]));
}

// ---------------- batched transpose to fp16 (one launch, 4 matrices) --------
// 32x33 tile body (R10-proven). Flat grid; compile-time dims per range.
#define TP_N0 3072   // w_qkv  [1024,3072] : 96 x 32 tiles
#define TP_N1 4096   // + w_out [1024,1024]: 32 x 32
#define TP_N2 8192   // + w_fc1 [1024,4096]: 128 x 32
#define TP_N3 12288  // + w_fc2 [4096,1024]: 32 x 128

__global__ __launch_bounds__(256) void transpose4_kernel(
    const float* __restrict__ s0, __half* __restrict__ d0,
    const float* __restrict__ s1, __half* __restrict__ d1,
    const float* __restrict__ s2, __half* __restrict__ d2,
    const float* __restrict__ s3, __half* __restrict__ d3)
{
    const int bid = blockIdx.x;
    const float* src; __half* dst; int R, C, bx, by;
    if (bid < TP_N0)      { src = s0; dst = d0; R = DMODEL; C = D3;
                            const int l = bid;          bx = l % 96;  by = l / 96;  }
    else if (bid < TP_N1) { src = s1; dst = d1; R = DMODEL; C = DMODEL;
                            const int l = bid - TP_N0;  bx = l % 32;  by = l / 32;  }
    else if (bid < TP_N2) { src = s2; dst = d2; R = DMODEL; C = INNER;
                            const int l = bid - TP_N1;  bx = l % 128; by = l / 128; }
    else                  { src = s3; dst = d3; R = INNER;  C = DMODEL;
                            const int l = bid - TP_N2;  bx = l % 32;  by = l / 32;  }

    __shared__ float tile[32][33];
    const int c0 = bx * 32, r0 = by * 32;
    const int tx = threadIdx.x & 31, ty = threadIdx.x >> 5;
#pragma unroll
    for (int i = 0; i < 4; i++)
        tile[ty + 8 * i][tx] = src[(size_t)(r0 + ty + 8 * i) * C + c0 + tx];
    __syncthreads();
#pragma unroll
    for (int i = 0; i < 4; i++)
        dst[(size_t)(c0 + ty + 8 * i) * R + r0 + tx] = __float2half(tile[tx][ty + 8 * i]);
}

// ---------------- fp16 tensor-core GEMM (R9/R10 locked optimum) -------------
// CT = output type, RT = residual type.
#define GS_ABYTES 8192
#define GS_STAGE  16384
#define GEMM_SMEM (4 * GS_STAGE)   // 65536

template<int EPI, typename CT, typename RT>
__global__ __launch_bounds__(128, 2) void hgemm_tc(
    const __half* __restrict__ A, const __half* __restrict__ Bt,
    const float* __restrict__ bias, const RT* __restrict__ res,
    CT* __restrict__ C, int M, int N, int K)
{
    extern __shared__ char smem[];
    const uint32_t sb = smem_u32(smem);
    const int tid = threadIdx.x, lane = tid & 31, wid = tid >> 5;
    const int warp_m = wid >> 1, warp_n = wid & 1;
    const int m0 = blockIdx.y * 128, n0 = blockIdx.x * 128;
    const int mb = warp_m * 64, nb = warp_n * 64;

    const int u = lane >> 3, ur = lane & 7;
    uint32_t aoff[4], boff[4];
#pragma unroll
    for (int i = 0; i < 4; i++)
        aoff[i] = (uint32_t)(mb + i * 16 + (u & 1) * 8 + ur) * 64 + (u >> 1) * 16;
#pragma unroll
    for (int p = 0; p < 4; p++)
        boff[p] = (uint32_t)(nb + p * 16 + (u >> 1) * 8 + ur) * 64 + (u & 1) * 16;

    float acc[4][8][4];
#pragma unroll
    for (int i = 0; i < 4; i++)
#pragma unroll
        for (int j = 0; j < 8; j++)
#pragma unroll
            for (int q = 0; q < 4; q++) acc[i][j][q] = 0.f;

    const int nk = K >> 5;

#define H_ISSUE(t)                                                             \
    do {                                                                       \
        const uint32_t sa_ = sb + ((t) & 3) * GS_STAGE;                        \
        const uint32_t sbB_ = sa_ + GS_ABYTES;                                 \
        _Pragma("unroll")                                                      \
        for (int i_ = 0; i_ < 4; i_++) {                                       \
            const int idx_ = tid + 128 * i_;                                   \
            const int r_ = idx_ >> 2, c_ = idx_ & 3;                           \
            const uint32_t so_ = SW64((uint32_t)r_ * 64 + c_ * 16);            \
            CP16(sa_ + so_, A + (size_t)(m0 + r_) * K + (t) * 32 + c_ * 8);    \
            CP16(sbB_ + so_, Bt + (size_t)(n0 + r_) * K + (t) * 32 + c_ * 8);  \
        }                                                                      \
        asm volatile("cp.async.commit_group;" ::: "memory");                   \
    } while (0)

    H_ISSUE(0); H_ISSUE(1); H_ISSUE(2);

    for (int t = 0; t < nk; t++) {
        const int rem = nk - 1 - t;
        if (rem >= 2)       asm volatile("cp.async.wait_group 2;" ::: "memory");
        else if (rem == 1)  asm volatile("cp.async.wait_group 1;" ::: "memory");
        else                asm volatile("cp.async.wait_group 0;" ::: "memory");
        __syncthreads();

        if (t + 3 < nk) H_ISSUE(t + 3);

        const uint32_t sa = sb + (t & 3) * GS_STAGE;
        const uint32_t sbB = sa + GS_ABYTES;
#pragma unroll
        for (int s = 0; s < 2; s++) {
            uint32_t af[4][4], bf[8][2];
#pragma unroll
            for (int i = 0; i < 4; i++)
                ldsm4(af[i], sa + SW64(aoff[i] + s * 32));
#pragma unroll
            for (int p = 0; p < 4; p++) {
                uint32_t r4[4];
                ldsm4(r4, sbB + SW64(boff[p] + s * 32));
                bf[2 * p][0] = r4[0]; bf[2 * p][1] = r4[1];
                bf[2 * p + 1][0] = r4[2]; bf[2 * p + 1][1] = r4[3];
            }
#pragma unroll
            for (int i = 0; i < 4; i++)
#pragma unroll
                for (int j = 0; j < 8; j++) mma16(acc[i][j], af[i], bf[j]);
        }
        __syncthreads();
    }
#undef H_ISSUE

    // ---- epilogue ----
    const int r0 = m0 + mb + (lane >> 2);
    const int c0 = n0 + nb + (lane & 3) * 2;
#pragma unroll
    for (int i = 0; i < 4; i++) {
#pragma unroll
        for (int j = 0; j < 8; j++) {
            const int col = c0 + j * 8;
            const float bx = bias[col], by = bias[col + 1];
#pragma unroll
            for (int hh = 0; hh < 2; hh++) {
                const int row = r0 + i * 16 + hh * 8;
                float vx = acc[i][j][hh * 2 + 0] + bx;
                float vy = acc[i][j][hh * 2 + 1] + by;
                if (EPI == 1) {
                    if (sizeof(RT) == 2) {
                        const __half2 rr = *(const __half2*)((const __half*)res + (size_t)row * N + col);
                        const float2 rf = __half22float2(rr);
                        vx += rf.x; vy += rf.y;
                    } else {
                        const float2 rr = *(const float2*)((const float*)res + (size_t)row * N + col);
                        vx += rr.x; vy += rr.y;
                    }
                }
                if (EPI == 2) {
                    vx = 0.5f * vx * (1.f + erff(vx * 0.70710678118654752f));
                    vy = 0.5f * vy * (1.f + erff(vy * 0.70710678118654752f));
                }
                CT* cp = C + (size_t)row * N + col;
                if (sizeof(CT) == 2) {
                    *(__half2*)cp = __floats2half2_rn(vx, vy);
                } else {
                    float2 v; v.x = vx; v.y = vy;
                    *(float2*)cp = v;
                }
            }
        }
    }
}

// ---------------- LayerNorm (templated input, fp16 output) ------------------
template<typename IT>
__global__ __launch_bounds__(256) void ln_kernel(
    const IT* __restrict__ x, const float* __restrict__ g,
    const float* __restrict__ b, __half* __restrict__ out)
{
    __shared__ float red[16];
    const size_t row = blockIdx.x;
    const int tid = threadIdx.x;

    float4 v;
    if (sizeof(IT) == 2) {
        const uint2 pk = ((const uint2*)((const __half*)x + row * DMODEL))[tid];
        const float2 a = __half22float2(*(const __half2*)&pk.x);
        const float2 c = __half22float2(*(const __half2*)&pk.y);
        v.x = a.x; v.y = a.y; v.z = c.x; v.w = c.y;
    } else {
        v = ((const float4*)((const float*)x + row * DMODEL))[tid];
    }
    float s1 = v.x + v.y + v.z + v.w;
    float s2 = v.x * v.x + v.y * v.y + v.z * v.z + v.w * v.w;
#pragma unroll
    for (int o = 16; o; o >>= 1) {
        s1 += __shfl_xor_sync(0xffffffffu, s1, o);
        s2 += __shfl_xor_sync(0xffffffffu, s2, o);
    }
    if ((tid & 31) == 0) { red[tid >> 5] = s1; red[8 + (tid >> 5)] = s2; }
    __syncthreads();
    if (tid < 32) {
        float a = (tid < 8) ? red[tid] : 0.f;
        float c = (tid < 8) ? red[8 + tid] : 0.f;
#pragma unroll
        for (int o = 4; o; o >>= 1) {
            a += __shfl_xor_sync(0xffffffffu, a, o);
            c += __shfl_xor_sync(0xffffffffu, c, o);
        }
        if (tid == 0) { red[0] = a; red[8] = c; }
    }
    __syncthreads();
    const float mu  = red[0] * (1.f / DMODEL);
    const float var = red[8] * (1.f / DMODEL) - mu * mu;
    const float r   = rsqrtf(var + 1e-5f);

    const float4 gg = ((const float4*)g)[tid];
    const float4 bb = ((const float4*)b)[tid];
    __half2 h01 = __floats2half2_rn((v.x - mu) * r * gg.x + bb.x,
                                    (v.y - mu) * r * gg.y + bb.y);
    __half2 h23 = __floats2half2_rn((v.z - mu) * r * gg.z + bb.z,
                                    (v.w - mu) * r * gg.w + bb.w);
    uint2 pk;
    pk.x = *(uint32_t*)&h01;
    pk.y = *(uint32_t*)&h23;
    *(uint2*)(out + row * DMODEL + tid * 4) = pk;
}

// ---------------- fp16 tensor-core flash attention (3-stage K/V) ------------
#define AT_KV_STAGE 16384
#define ATT_SMEM (16384 + 3 * AT_KV_STAGE)   // 65536

__global__ __launch_bounds__(256) void attn_h_kernel(
    const __half* __restrict__ qkv, __half* __restrict__ o)
{
    extern __shared__ char sm[];
    const uint32_t uQ = smem_u32(sm);
    const uint32_t uKV = uQ + 16384;

    const int tid = threadIdx.x, lane = tid & 31, w = tid >> 5;
    const int bh = blockIdx.y;
    const int b = bh >> 4, h = bh & 15;
    const int qb = (int)gridDim.x - 1 - (int)blockIdx.x;
    const int q0 = qb * 128;
    const size_t bL = (size_t)b * SEQ;

    const int u = lane >> 3, ur = lane & 7;
    const uint32_t aoff = (uint32_t)(w * 16 + (u & 1) * 8 + ur) * 128 + (u >> 1) * 16;
    uint32_t boffK[4];
#pragma unroll
    for (int p = 0; p < 4; p++)
        boffK[p] = (uint32_t)(p * 16 + (u >> 1) * 8 + ur) * 128 + (u & 1) * 16;
    uint32_t boffV[4];
#pragma unroll
    for (int p = 0; p < 4; p++)
        boffV[p] = (uint32_t)((u & 1) * 8 + ur) * 128 + p * 32 + (u >> 1) * 16;

#define A_ISSUE(kb)                                                            \
    do {                                                                       \
        const uint32_t uS_ = uKV + ((kb) % 3) * AT_KV_STAGE;                   \
        _Pragma("unroll")                                                      \
        for (int i_ = 0; i_ < 2; i_++) {                                       \
            const int idx_ = tid + 256 * i_;                                   \
            const int r_ = idx_ >> 3, c_ = idx_ & 7;                           \
            const uint32_t so_ = SW128((uint32_t)r_ * 128 + c_ * 16);          \
            const __half* kp_ = qkv + (bL + (kb) * 64 + r_) * D3 + DMODEL      \
                                + h * HDIM + c_ * 8;                           \
            CP16(uS_ + so_, kp_);                                              \
            CP16(uS_ + 8192 + so_, kp_ + DMODEL);                              \
        }                                                                      \
        asm volatile("cp.async.commit_group;" ::: "memory");                   \
    } while (0)

    const int nkb = 2 * qb + 2;

    A_ISSUE(0);
    {
#pragma unroll
        for (int i = 0; i < 4; i++) {
            const int idx = tid + 256 * i;
            const int r = idx >> 3, c = idx & 7;
            CP16(uQ + SW128((uint32_t)r * 128 + c * 16),
                 qkv + (bL + q0 + r) * D3 + h * HDIM + c * 8);
        }
        asm volatile("cp.async.commit_group;" ::: "memory");
    }
    if (nkb > 1) A_ISSUE(1);
    if (nkb > 1) asm volatile("cp.async.wait_group 1;" ::: "memory");
    else         asm volatile("cp.async.wait_group 0;" ::: "memory");
    __syncthreads();

    uint32_t qf[4][4];
#pragma unroll
    for (int s = 0; s < 4; s++) ldsm4(qf[s], uQ + SW128(aoff + s * 32));

    float oa[8][4];
#pragma unroll
    for (int n = 0; n < 8; n++)
#pragma unroll
        for (int q = 0; q < 4; q++) oa[n][q] = 0.f;
    float m_lo = -1e30f, m_hi = -1e30f, l_lo = 0.f, l_hi = 0.f;

    const int grow_lo = q0 + w * 16 + (lane >> 2);
    const int grow_hi = grow_lo + 8;

    for (int kb = 0; kb < nkb; kb++) {
        if (kb + 2 < nkb) A_ISSUE(kb + 2);
        const int rem = nkb - 1 - kb;
        if (rem >= 2)      asm volatile("cp.async.wait_group 2;" ::: "memory");
        else if (rem == 1) asm volatile("cp.async.wait_group 1;" ::: "memory");
        else               asm volatile("cp.async.wait_group 0;" ::: "memory");
        __syncthreads();

        const uint32_t uK = uKV + (kb % 3) * AT_KV_STAGE;
        const uint32_t uV = uK + 8192;

        float sc[8][4];
#pragma unroll
        for (int n = 0; n < 8; n++)
#pragma unroll
            for (int q = 0; q < 4; q++) sc[n][q] = 0.f;
#pragma unroll
        for (int s = 0; s < 4; s++) {
            uint32_t bf[8][2];
#pragma unroll
            for (int p = 0; p < 4; p++) {
                uint32_t r4[4];
                ldsm4(r4, uK + SW128(boffK[p] + s * 32));
                bf[2 * p][0] = r4[0]; bf[2 * p][1] = r4[1];
                bf[2 * p + 1][0] = r4[2]; bf[2 * p + 1][1] = r4[3];
            }
#pragma unroll
            for (int n = 0; n < 8; n++) mma16(sc[n], qf[s], bf[n]);
        }

        const bool need_mask = (kb >= 2 * qb);
        const int c0g = kb * 64 + (lane & 3) * 2;
#pragma unroll
        for (int n = 0; n < 8; n++) {
            const int col0 = c0g + n * 8, col1 = col0 + 1;
            float s0 = sc[n][0] * 0.125f, s1 = sc[n][1] * 0.125f;
            float s2 = sc[n][2] * 0.125f, s3 = sc[n][3] * 0.125f;
            if (need_mask) {
                if (col0 > grow_lo) s0 = -1e30f;
                if (col1 > grow_lo) s1 = -1e30f;
                if (col0 > grow_hi) s2 = -1e30f;
                if (col1 > grow_hi) s3 = -1e30f;
            }
            sc[n][0] = s0; sc[n][1] = s1; sc[n][2] = s2; sc[n][3] = s3;
        }

        float bm_lo = -1e30f, bm_hi = -1e30f;
#pragma unroll
        for (int n = 0; n < 8; n++) {
            bm_lo = fmaxf(bm_lo, fmaxf(sc[n][0], sc[n][1]));
            bm_hi = fmaxf(bm_hi, fmaxf(sc[n][2], sc[n][3]));
        }
        bm_lo = fmaxf(bm_lo, __shfl_xor_sync(0xffffffffu, bm_lo, 1));
        bm_lo = fmaxf(bm_lo, __shfl_xor_sync(0xffffffffu, bm_lo, 2));
        bm_hi = fmaxf(bm_hi, __shfl_xor_sync(0xffffffffu, bm_hi, 1));
        bm_hi = fmaxf(bm_hi, __shfl_xor_sync(0xffffffffu, bm_hi, 2));
        const float mn_lo = fmaxf(m_lo, bm_lo);
        const float mn_hi = fmaxf(m_hi, bm_hi);
        const float f_lo = __expf(m_lo - mn_lo);
        const float f_hi = __expf(m_hi - mn_hi);
        m_lo = mn_lo; m_hi = mn_hi;

        float ps_lo = 0.f, ps_hi = 0.f;
#pragma unroll
        for (int n = 0; n < 8; n++) {
            sc[n][0] = __expf(sc[n][0] - mn_lo);
            sc[n][1] = __expf(sc[n][1] - mn_lo);
            sc[n][2] = __expf(sc[n][2] - mn_hi);
            sc[n][3] = __expf(sc[n][3] - mn_hi);
            ps_lo += sc[n][0] + sc[n][1];
            ps_hi += sc[n][2] + sc[n][3];
        }
        ps_lo += __shfl_xor_sync(0xffffffffu, ps_lo, 1);
        ps_lo += __shfl_xor_sync(0xffffffffu, ps_lo, 2);
        ps_hi += __shfl_xor_sync(0xffffffffu, ps_hi, 1);
        ps_hi += __shfl_xor_sync(0xffffffffu, ps_hi, 2);
        l_lo = l_lo * f_lo + ps_lo;
        l_hi = l_hi * f_hi + ps_hi;

#pragma unroll
        for (int n = 0; n < 8; n++) {
            oa[n][0] *= f_lo; oa[n][1] *= f_lo;
            oa[n][2] *= f_hi; oa[n][3] *= f_hi;
        }

        {
            const uint32_t plo = (uint32_t)(w * 16 + (lane >> 2)) * 128 + (lane & 3) * 4;
            const uint32_t phi = plo + 8 * 128;
#pragma unroll
            for (int n = 0; n < 8; n++) {
                *(__half2*)(sm + SW128(plo + n * 16)) = __floats2half2_rn(sc[n][0], sc[n][1]);
                *(__half2*)(sm + SW128(phi + n * 16)) = __floats2half2_rn(sc[n][2], sc[n][3]);
            }
        }
        __syncwarp();

#pragma unroll
        for (int s = 0; s < 4; s++) {
            uint32_t ap[4];
            ldsm4(ap, uQ + SW128(aoff + s * 32));
#pragma unroll
            for (int p = 0; p < 4; p++) {
                uint32_t r4[4];
                ldsm4t(r4, uV + SW128(boffV[p] + s * 16 * 128));
                uint32_t b0[2] = { r4[0], r4[1] };
                uint32_t b1[2] = { r4[2], r4[3] };
                mma16(oa[2 * p], ap, b0);
                mma16(oa[2 * p + 1], ap, b1);
            }
        }
        __syncthreads();
    }
#undef A_ISSUE

    const float inv_lo = 1.f / l_lo, inv_hi = 1.f / l_hi;
    __half* orow_lo = o + (bL + grow_lo) * DMODEL + h * HDIM + (lane & 3) * 2;
    __half* orow_hi = o + (bL + grow_hi) * DMODEL + h * HDIM + (lane & 3) * 2;
#pragma unroll
    for (int n = 0; n < 8; n++) {
        *(__half2*)(orow_lo + n * 8) = __floats2half2_rn(oa[n][0] * inv_lo, oa[n][1] * inv_lo);
        *(__half2*)(orow_hi + n * 8) = __floats2half2_rn(oa[n][2] * inv_hi, oa[n][3] * inv_hi);
    }
}

// ---------------- launcher ----------------
extern "C" void kernel_launch(void* const* d_in, const int* in_sizes, int n_in,
                              void* d_out, int out_size)
{
    const float* x     = (const float*)d_in[0];
    const float* w_qkv = (const float*)d_in[1];
    const float* b_qkv = (const float*)d_in[2];
    const float* w_out = (const float*)d_in[3];
    const float* b_out = (const float*)d_in[4];
    const float* w_fc1 = (const float*)d_in[5];
    const float* b_fc1 = (const float*)d_in[6];
    const float* w_fc2 = (const float*)d_in[7];
    const float* b_fc2 = (const float*)d_in[8];
    const float* ln1_g = (const float*)d_in[9];
    const float* ln1_b = (const float*)d_in[10];
    const float* ln2_g = (const float*)d_in[11];
    const float* ln2_b = (const float*)d_in[12];
    float* out = (float*)d_out;

    __half *h, *qkv, *o, *x1h, *fc1, *wT;
    cudaGetSymbolAddress((void**)&h,   g_hh);
    cudaGetSymbolAddress((void**)&qkv, g_qkvh);
    cudaGetSymbolAddress((void**)&o,   g_oh);
    cudaGetSymbolAddress((void**)&x1h, g_x1h);
    cudaGetSymbolAddress((void**)&fc1, g_fc1h);
    cudaGetSymbolAddress((void**)&wT,  g_wTh);

    __half* wqkvT = wT;                       // [3072,1024]
    __half* woutT = wqkvT + 3072 * 1024;      // [1024,1024]
    __half* wfc1T = woutT + 1024 * 1024;      // [4096,1024]
    __half* wfc2T = wfc1T + 4096 * 1024;      // [1024,4096]

    cudaFuncSetAttribute((const void*)hgemm_tc<0, __half, float>,  cudaFuncAttributeMaxDynamicSharedMemorySize, GEMM_SMEM);
    cudaFuncSetAttribute((const void*)hgemm_tc<1, __half, float>,  cudaFuncAttributeMaxDynamicSharedMemorySize, GEMM_SMEM);
    cudaFuncSetAttribute((const void*)hgemm_tc<2, __half, float>,  cudaFuncAttributeMaxDynamicSharedMemorySize, GEMM_SMEM);
    cudaFuncSetAttribute((const void*)hgemm_tc<1, float, __half>,  cudaFuncAttributeMaxDynamicSharedMemorySize, GEMM_SMEM);
    cudaFuncSetAttribute(attn_h_kernel, cudaFuncAttributeMaxDynamicSharedMemorySize, ATT_SMEM);

    // 0) transpose all weights in one launch
    transpose4_kernel<<<TP_N3, 256>>>(w_qkv, wqkvT, w_out, woutT,
                                      w_fc1, wfc1T, w_fc2, wfc2T);

    // 1) LN1 (fp32 in, fp16 out)
    ln_kernel<float><<<MROWS, 256>>>(x, ln1_g, ln1_b, h);

    // 2) QKV projection (fp16 out)
    hgemm_tc<0, __half, float><<<dim3(D3 / 128, MROWS / 128), 128, GEMM_SMEM>>>(
        h, wqkvT, b_qkv, nullptr, qkv, MROWS, D3, DMODEL);

    // 3) causal attention
    attn_h_kernel<<<dim3(SEQ / 128, BATCH * NHEAD), 256, ATT_SMEM>>>(qkv, o);

    // 4) out projection + residual(x, fp32) -> x1 (fp16)
    hgemm_tc<1, __half, float><<<dim3(DMODEL / 128, MROWS / 128), 128, GEMM_SMEM>>>(
        o, woutT, b_out, x, x1h, MROWS, DMODEL, DMODEL);

    // 5) LN2 (fp16 in, fp16 out)
    ln_kernel<__half><<<MROWS, 256>>>(x1h, ln2_g, ln2_b, h);

    // 6) FC1 + exact GELU (fp16 out)
    hgemm_tc<2, __half, float><<<dim3(INNER / 128, MROWS / 128), 128, GEMM_SMEM>>>(
        h, wfc1T, b_fc1, nullptr, fc1, MROWS, INNER, DMODEL);

    // 7) FC2 + residual(x1, fp16) -> out (fp32)
    hgemm_tc<1, float, __half><<<dim3(DMODEL / 128, MROWS / 128), 128, GEMM_SMEM>>>(
        fc1, wfc2T, b_fc2, x1h, out, MROWS, DMODEL, INNER);
}

// round 16
// speedup vs baseline: 1.0348x; 1.0221x over previous
#include <cuda_runtime.h>
#include <cuda_fp16.h>
#include <cuda_bf16.h>
#include <math.h>
#include <cstdint>

// Problem constants
#define BATCH 2
#define SEQ   2048
#define MROWS (BATCH*SEQ)       // 4096
#define DMODEL 1024
#define D3    (3*DMODEL)        // 3072
#define INNER (4*DMODEL)        // 4096
#define NHEAD 16
#define HDIM  64

// ---------------- scratch (device globals; no allocations allowed) ----------
__device__ __half g_hh  [MROWS*DMODEL];   // LN output (fp16)
__device__ __half g_qkvh[MROWS*D3];       // QKV projection (fp16)
__device__ __half g_oh  [MROWS*DMODEL];   // attention output (fp16)
__device__ __half g_x1h [MROWS*DMODEL];   // residual after attention (fp16)
__device__ __half g_fc1h[MROWS*INNER];    // FC1+GELU output (fp16)
__device__ __half g_wTh [12*1024*1024];   // transposed fp16 weights

// ---------------- helpers ----------------
__device__ __forceinline__ uint32_t smem_u32(const void* p) {
    uint32_t a;
    asm("{ .reg .u64 t; cvta.to.shared.u64 t, %1; cvt.u32.u64 %0, t; }" : "=r"(a) : "l"(p));
    return a;
}
#define SW64(x)  ((x) ^ (((x) >> 3) & 0x30))
#define SW128(x) ((x) ^ (((x) >> 3) & 0x70))
#define CP16(sa, ga) \
    asm volatile("cp.async.cg.shared.global [%0], [%1], 16;" :: "r"(sa), "l"(ga) : "memory")

__device__ __forceinline__ void ldsm4(uint32_t* r, uint32_t a) {
    asm volatile("ldmatrix.sync.aligned.m8n8.x4.shared.b16 {%0,%1,%2,%3}, [%4];"
        : "=r"(r[0]), "=r"(r[1]), "=r"(r[2]), "=r"(r[3]) : "r"(a));
}
__device__ __forceinline__ void ldsm4t(uint32_t* r, uint32_t a) {
    asm volatile("ldmatrix.sync.aligned.m8n8.x4.trans.shared.b16 {%0,%1,%2,%3}, [%4];"
        : "=r"(r[0]), "=r"(r[1]), "=r"(r[2]), "=r"(r[3]) : "r"(a));
}
__device__ __forceinline__ void mma16(float* d, const uint32_t* a, const uint32_t* b) {
    asm volatile("mma.sync.aligned.m16n8k16.row.col.f32.f16.f16.f32 "
        "{%0,%1,%2,%3}, {%4,%5,%6,%7}, {%8,%9}, {%0,%1,%2,%3};"
        : "+f"(d[0]), "+f"(d[1]), "+f"(d[2]), "+f"(d[3])
        : "r"(a[0]), "r"(a[1]), "r"(a[2]), "r"(a[3]), "r"(b[0]), "r"(b[1]));
}

// ---------------- batched transpose to fp16 (one launch, 4 matrices) --------
#define TP_N0 3072
#define TP_N1 4096
#define TP_N2 8192
#define TP_N3 12288

__global__ __launch_bounds__(256) void transpose4_kernel(
    const float* __restrict__ s0, __half* __restrict__ d0,
    const float* __restrict__ s1, __half* __restrict__ d1,
    const float* __restrict__ s2, __half* __restrict__ d2,
    const float* __restrict__ s3, __half* __restrict__ d3)
{
    const int bid = blockIdx.x;
    const float* src; __half* dst; int R, C, bx, by;
    if (bid < TP_N0)      { src = s0; dst = d0; R = DMODEL; C = D3;
                            const int l = bid;          bx = l % 96;  by = l / 96;  }
    else if (bid < TP_N1) { src = s1; dst = d1; R = DMODEL; C = DMODEL;
                            const int l = bid - TP_N0;  bx = l % 32;  by = l / 32;  }
    else if (bid < TP_N2) { src = s2; dst = d2; R = DMODEL; C = INNER;
                            const int l = bid - TP_N1;  bx = l % 128; by = l / 128; }
    else                  { src = s3; dst = d3; R = INNER;  C = DMODEL;
                            const int l = bid - TP_N2;  bx = l % 32;  by = l / 32;  }

    __shared__ float tile[32][33];
    const int c0 = bx * 32, r0 = by * 32;
    const int tx = threadIdx.x & 31, ty = threadIdx.x >> 5;
#pragma unroll
    for (int i = 0; i < 4; i++)
        tile[ty + 8 * i][tx] = src[(size_t)(r0 + ty + 8 * i) * C + c0 + tx];
    __syncthreads();
#pragma unroll
    for (int i = 0; i < 4; i++)
        dst[(size_t)(c0 + ty + 8 * i) * R + r0 + tx] = __float2half(tile[tx][ty + 8 * i]);
}

// ---------------- fp16 tensor-core GEMM (locked optimum) --------------------
#define GS_ABYTES 8192
#define GS_STAGE  16384
#define GEMM_SMEM (4 * GS_STAGE)   // 65536

template<int EPI, typename CT, typename RT>
__global__ __launch_bounds__(128, 2) void hgemm_tc(
    const __half* __restrict__ A, const __half* __restrict__ Bt,
    const float* __restrict__ bias, const RT* __restrict__ res,
    CT* __restrict__ C, int M, int N, int K)
{
    extern __shared__ char smem[];
    const uint32_t sb = smem_u32(smem);
    const int tid = threadIdx.x, lane = tid & 31, wid = tid >> 5;
    const int warp_m = wid >> 1, warp_n = wid & 1;
    const int m0 = blockIdx.y * 128, n0 = blockIdx.x * 128;
    const int mb = warp_m * 64, nb = warp_n * 64;

    const int u = lane >> 3, ur = lane & 7;
    uint32_t aoff[4], boff[4];
#pragma unroll
    for (int i = 0; i < 4; i++)
        aoff[i] = (uint32_t)(mb + i * 16 + (u & 1) * 8 + ur) * 64 + (u >> 1) * 16;
#pragma unroll
    for (int p = 0; p < 4; p++)
        boff[p] = (uint32_t)(nb + p * 16 + (u >> 1) * 8 + ur) * 64 + (u & 1) * 16;

    float acc[4][8][4];
#pragma unroll
    for (int i = 0; i < 4; i++)
#pragma unroll
        for (int j = 0; j < 8; j++)
#pragma unroll
            for (int q = 0; q < 4; q++) acc[i][j][q] = 0.f;

    const int nk = K >> 5;

#define H_ISSUE(t)                                                             \
    do {                                                                       \
        const uint32_t sa_ = sb + ((t) & 3) * GS_STAGE;                        \
        const uint32_t sbB_ = sa_ + GS_ABYTES;                                 \
        _Pragma("unroll")                                                      \
        for (int i_ = 0; i_ < 4; i_++) {                                       \
            const int idx_ = tid + 128 * i_;                                   \
            const int r_ = idx_ >> 2, c_ = idx_ & 3;                           \
            const uint32_t so_ = SW64((uint32_t)r_ * 64 + c_ * 16);            \
            CP16(sa_ + so_, A + (size_t)(m0 + r_) * K + (t) * 32 + c_ * 8);    \
            CP16(sbB_ + so_, Bt + (size_t)(n0 + r_) * K + (t) * 32 + c_ * 8);  \
        }                                                                      \
        asm volatile("cp.async.commit_group;" ::: "memory");                   \
    } while (0)

    H_ISSUE(0); H_ISSUE(1); H_ISSUE(2);

    for (int t = 0; t < nk; t++) {
        const int rem = nk - 1 - t;
        if (rem >= 2)       asm volatile("cp.async.wait_group 2;" ::: "memory");
        else if (rem == 1)  asm volatile("cp.async.wait_group 1;" ::: "memory");
        else                asm volatile("cp.async.wait_group 0;" ::: "memory");
        __syncthreads();

        if (t + 3 < nk) H_ISSUE(t + 3);

        const uint32_t sa = sb + (t & 3) * GS_STAGE;
        const uint32_t sbB = sa + GS_ABYTES;
#pragma unroll
        for (int s = 0; s < 2; s++) {
            uint32_t af[4][4], bf[8][2];
#pragma unroll
            for (int i = 0; i < 4; i++)
                ldsm4(af[i], sa + SW64(aoff[i] + s * 32));
#pragma unroll
            for (int p = 0; p < 4; p++) {
                uint32_t r4[4];
                ldsm4(r4, sbB + SW64(boff[p] + s * 32));
                bf[2 * p][0] = r4[0]; bf[2 * p][1] = r4[1];
                bf[2 * p + 1][0] = r4[2]; bf[2 * p + 1][1] = r4[3];
            }
#pragma unroll
            for (int i = 0; i < 4; i++)
#pragma unroll
                for (int j = 0; j < 8; j++) mma16(acc[i][j], af[i], bf[j]);
        }
        __syncthreads();
    }
#undef H_ISSUE

    // ---- epilogue ----
    const int r0 = m0 + mb + (lane >> 2);
    const int c0 = n0 + nb + (lane & 3) * 2;
#pragma unroll
    for (int i = 0; i < 4; i++) {
#pragma unroll
        for (int j = 0; j < 8; j++) {
            const int col = c0 + j * 8;
            const float bx = bias[col], by = bias[col + 1];
#pragma unroll
            for (int hh = 0; hh < 2; hh++) {
                const int row = r0 + i * 16 + hh * 8;
                float vx = acc[i][j][hh * 2 + 0] + bx;
                float vy = acc[i][j][hh * 2 + 1] + by;
                if (EPI == 1) {
                    if (sizeof(RT) == 2) {
                        const __half2 rr = *(const __half2*)((const __half*)res + (size_t)row * N + col);
                        const float2 rf = __half22float2(rr);
                        vx += rf.x; vy += rf.y;
                    } else {
                        const float2 rr = *(const float2*)((const float*)res + (size_t)row * N + col);
                        vx += rr.x; vy += rr.y;
                    }
                }
                if (EPI == 2) {
                    vx = 0.5f * vx * (1.f + erff(vx * 0.70710678118654752f));
                    vy = 0.5f * vy * (1.f + erff(vy * 0.70710678118654752f));
                }
                CT* cp = C + (size_t)row * N + col;
                if (sizeof(CT) == 2) {
                    *(__half2*)cp = __floats2half2_rn(vx, vy);
                } else {
                    float2 v; v.x = vx; v.y = vy;
                    *(float2*)cp = v;
                }
            }
        }
    }
}

// ---------------- LayerNorm (templated input, fp16 output) ------------------
template<typename IT>
__global__ __launch_bounds__(256) void ln_kernel(
    const IT* __restrict__ x, const float* __restrict__ g,
    const float* __restrict__ b, __half* __restrict__ out)
{
    __shared__ float red[16];
    const size_t row = blockIdx.x;
    const int tid = threadIdx.x;

    float4 v;
    if (sizeof(IT) == 2) {
        const uint2 pk = ((const uint2*)((const __half*)x + row * DMODEL))[tid];
        const float2 a = __half22float2(*(const __half2*)&pk.x);
        const float2 c = __half22float2(*(const __half2*)&pk.y);
        v.x = a.x; v.y = a.y; v.z = c.x; v.w = c.y;
    } else {
        v = ((const float4*)((const float*)x + row * DMODEL))[tid];
    }
    float s1 = v.x + v.y + v.z + v.w;
    float s2 = v.x * v.x + v.y * v.y + v.z * v.z + v.w * v.w;
#pragma unroll
    for (int o = 16; o; o >>= 1) {
        s1 += __shfl_xor_sync(0xffffffffu, s1, o);
        s2 += __shfl_xor_sync(0xffffffffu, s2, o);
    }
    if ((tid & 31) == 0) { red[tid >> 5] = s1; red[8 + (tid >> 5)] = s2; }
    __syncthreads();
    if (tid < 32) {
        float a = (tid < 8) ? red[tid] : 0.f;
        float c = (tid < 8) ? red[8 + tid] : 0.f;
#pragma unroll
        for (int o = 4; o; o >>= 1) {
            a += __shfl_xor_sync(0xffffffffu, a, o);
            c += __shfl_xor_sync(0xffffffffu, c, o);
        }
        if (tid == 0) { red[0] = a; red[8] = c; }
    }
    __syncthreads();
    const float mu  = red[0] * (1.f / DMODEL);
    const float var = red[8] * (1.f / DMODEL) - mu * mu;
    const float r   = rsqrtf(var + 1e-5f);

    const float4 gg = ((const float4*)g)[tid];
    const float4 bb = ((const float4*)b)[tid];
    __half2 h01 = __floats2half2_rn((v.x - mu) * r * gg.x + bb.x,
                                    (v.y - mu) * r * gg.y + bb.y);
    __half2 h23 = __floats2half2_rn((v.z - mu) * r * gg.z + bb.z,
                                    (v.w - mu) * r * gg.w + bb.w);
    uint2 pk;
    pk.x = *(uint32_t*)&h01;
    pk.y = *(uint32_t*)&h23;
    *(uint2*)(out + row * DMODEL + tid * 4) = pk;
}

// ---------------- fp16 flash attention (64-row tiles, 4 warps, 3-stage) -----
// Smem: Q/P [64][64]h = 8KB, then 3 stages of (K 8KB + V 8KB) = 48KB. 56KB tot.
#define AT_KV_STAGE 16384
#define ATT_SMEM (8192 + 3 * AT_KV_STAGE)   // 57344

__global__ __launch_bounds__(128) void attn_h_kernel(
    const __half* __restrict__ qkv, __half* __restrict__ o)
{
    extern __shared__ char sm[];
    const uint32_t uQ = smem_u32(sm);
    const uint32_t uKV = uQ + 8192;

    const int tid = threadIdx.x, lane = tid & 31, w = tid >> 5;   // w: 0..3
    const int bh = blockIdx.y;
    const int b = bh >> 4, h = bh & 15;
    const int qb = (int)gridDim.x - 1 - (int)blockIdx.x;   // heavy tiles first
    const int q0 = qb * 64;
    const size_t bL = (size_t)b * SEQ;

    const int u = lane >> 3, ur = lane & 7;
    const uint32_t aoff = (uint32_t)(w * 16 + (u & 1) * 8 + ur) * 128 + (u >> 1) * 16;
    uint32_t boffK[4];
#pragma unroll
    for (int p = 0; p < 4; p++)
        boffK[p] = (uint32_t)(p * 16 + (u >> 1) * 8 + ur) * 128 + (u & 1) * 16;
    uint32_t boffV[4];
#pragma unroll
    for (int p = 0; p < 4; p++)
        boffV[p] = (uint32_t)((u & 1) * 8 + ur) * 128 + p * 32 + (u >> 1) * 16;

    // K/V for block kb -> stage kb%3 (128 threads: 4 iters x 2 CP16)
#define A_ISSUE(kb)                                                            \
    do {                                                                       \
        const uint32_t uS_ = uKV + ((kb) % 3) * AT_KV_STAGE;                   \
        _Pragma("unroll")                                                      \
        for (int i_ = 0; i_ < 4; i_++) {                                       \
            const int idx_ = tid + 128 * i_;                                   \
            const int r_ = idx_ >> 3, c_ = idx_ & 7;                           \
            const uint32_t so_ = SW128((uint32_t)r_ * 128 + c_ * 16);          \
            const __half* kp_ = qkv + (bL + (kb) * 64 + r_) * D3 + DMODEL      \
                                + h * HDIM + c_ * 8;                           \
            CP16(uS_ + so_, kp_);                                              \
            CP16(uS_ + 8192 + so_, kp_ + DMODEL);                              \
        }                                                                      \
        asm volatile("cp.async.commit_group;" ::: "memory");                   \
    } while (0)

    const int nkb = qb + 1;

    A_ISSUE(0);
    {
        // Q tile: 64 rows x 128B = 512 chunks / 128 threads = 4 each
#pragma unroll
        for (int i = 0; i < 4; i++) {
            const int idx = tid + 128 * i;
            const int r = idx >> 3, c = idx & 7;
            CP16(uQ + SW128((uint32_t)r * 128 + c * 16),
                 qkv + (bL + q0 + r) * D3 + h * HDIM + c * 8);
        }
        asm volatile("cp.async.commit_group;" ::: "memory");
    }
    if (nkb > 1) A_ISSUE(1);
    if (nkb > 1) asm volatile("cp.async.wait_group 1;" ::: "memory");
    else         asm volatile("cp.async.wait_group 0;" ::: "memory");
    __syncthreads();

    uint32_t qf[4][4];
#pragma unroll
    for (int s = 0; s < 4; s++) ldsm4(qf[s], uQ + SW128(aoff + s * 32));

    float oa[8][4];
#pragma unroll
    for (int n = 0; n < 8; n++)
#pragma unroll
        for (int q = 0; q < 4; q++) oa[n][q] = 0.f;
    float m_lo = -1e30f, m_hi = -1e30f, l_lo = 0.f, l_hi = 0.f;

    const int grow_lo = q0 + w * 16 + (lane >> 2);
    const int grow_hi = grow_lo + 8;

    for (int kb = 0; kb < nkb; kb++) {
        if (kb + 2 < nkb) A_ISSUE(kb + 2);
        const int rem = nkb - 1 - kb;
        if (rem >= 2)      asm volatile("cp.async.wait_group 2;" ::: "memory");
        else if (rem == 1) asm volatile("cp.async.wait_group 1;" ::: "memory");
        else               asm volatile("cp.async.wait_group 0;" ::: "memory");
        __syncthreads();

        const uint32_t uK = uKV + (kb % 3) * AT_KV_STAGE;
        const uint32_t uV = uK + 8192;

        float sc[8][4];
#pragma unroll
        for (int n = 0; n < 8; n++)
#pragma unroll
            for (int q = 0; q < 4; q++) sc[n][q] = 0.f;
#pragma unroll
        for (int s = 0; s < 4; s++) {
            uint32_t bf[8][2];
#pragma unroll
            for (int p = 0; p < 4; p++) {
                uint32_t r4[4];
                ldsm4(r4, uK + SW128(boffK[p] + s * 32));
                bf[2 * p][0] = r4[0]; bf[2 * p][1] = r4[1];
                bf[2 * p + 1][0] = r4[2]; bf[2 * p + 1][1] = r4[3];
            }
#pragma unroll
            for (int n = 0; n < 8; n++) mma16(sc[n], qf[s], bf[n]);
        }

        const bool need_mask = (kb == qb);
        const int c0g = kb * 64 + (lane & 3) * 2;
#pragma unroll
        for (int n = 0; n < 8; n++) {
            const int col0 = c0g + n * 8, col1 = col0 + 1;
            float s0 = sc[n][0] * 0.125f, s1 = sc[n][1] * 0.125f;
            float s2 = sc[n][2] * 0.125f, s3 = sc[n][3] * 0.125f;
            if (need_mask) {
                if (col0 > grow_lo) s0 = -1e30f;
                if (col1 > grow_lo) s1 = -1e30f;
                if (col0 > grow_hi) s2 = -1e30f;
                if (col1 > grow_hi) s3 = -1e30f;
            }
            sc[n][0] = s0; sc[n][1] = s1; sc[n][2] = s2; sc[n][3] = s3;
        }

        float bm_lo = -1e30f, bm_hi = -1e30f;
#pragma unroll
        for (int n = 0; n < 8; n++) {
            bm_lo = fmaxf(bm_lo, fmaxf(sc[n][0], sc[n][1]));
            bm_hi = fmaxf(bm_hi, fmaxf(sc[n][2], sc[n][3]));
        }
        bm_lo = fmaxf(bm_lo, __shfl_xor_sync(0xffffffffu, bm_lo, 1));
        bm_lo = fmaxf(bm_lo, __shfl_xor_sync(0xffffffffu, bm_lo, 2));
        bm_hi = fmaxf(bm_hi, __shfl_xor_sync(0xffffffffu, bm_hi, 1));
        bm_hi = fmaxf(bm_hi, __shfl_xor_sync(0xffffffffu, bm_hi, 2));
        const float mn_lo = fmaxf(m_lo, bm_lo);
        const float mn_hi = fmaxf(m_hi, bm_hi);
        const float f_lo = __expf(m_lo - mn_lo);
        const float f_hi = __expf(m_hi - mn_hi);
        m_lo = mn_lo; m_hi = mn_hi;

        float ps_lo = 0.f, ps_hi = 0.f;
#pragma unroll
        for (int n = 0; n < 8; n++) {
            sc[n][0] = __expf(sc[n][0] - mn_lo);
            sc[n][1] = __expf(sc[n][1] - mn_lo);
            sc[n][2] = __expf(sc[n][2] - mn_hi);
            sc[n][3] = __expf(sc[n][3] - mn_hi);
            ps_lo += sc[n][0] + sc[n][1];
            ps_hi += sc[n][2] + sc[n][3];
        }
        ps_lo += __shfl_xor_sync(0xffffffffu, ps_lo, 1);
        ps_lo += __shfl_xor_sync(0xffffffffu, ps_lo, 2);
        ps_hi += __shfl_xor_sync(0xffffffffu, ps_hi, 1);
        ps_hi += __shfl_xor_sync(0xffffffffu, ps_hi, 2);
        l_lo = l_lo * f_lo + ps_lo;
        l_hi = l_hi * f_hi + ps_hi;

#pragma unroll
        for (int n = 0; n < 8; n++) {
            oa[n][0] *= f_lo; oa[n][1] *= f_lo;
            oa[n][2] *= f_hi; oa[n][3] *= f_hi;
        }

        // ---- write P (fp16) into Q region (warp-private rows) ----
        {
            const uint32_t plo = (uint32_t)(w * 16 + (lane >> 2)) * 128 + (lane & 3) * 4;
            const uint32_t phi = plo + 8 * 128;
#pragma unroll
            for (int n = 0; n < 8; n++) {
                *(__half2*)(sm + SW128(plo + n * 16)) = __floats2half2_rn(sc[n][0], sc[n][1]);
                *(__half2*)(sm + SW128(phi + n * 16)) = __floats2half2_rn(sc[n][2], sc[n][3]);
            }
        }
        __syncwarp();

        // ---- O += P @ V ----
#pragma unroll
        for (int s = 0; s < 4; s++) {
            uint32_t ap[4];
            ldsm4(ap, uQ + SW128(aoff + s * 32));
#pragma unroll
            for (int p = 0; p < 4; p++) {
                uint32_t r4[4];
                ldsm4t(r4, uV + SW128(boffV[p] + s * 16 * 128));
                uint32_t b0[2] = { r4[0], r4[1] };
                uint32_t b1[2] = { r4[2], r4[3] };
                mma16(oa[2 * p], ap, b0);
                mma16(oa[2 * p + 1], ap, b1);
            }
        }
        __syncthreads();
    }
#undef A_ISSUE

    const float inv_lo = 1.f / l_lo, inv_hi = 1.f / l_hi;
    __half* orow_lo = o + (bL + grow_lo) * DMODEL + h * HDIM + (lane & 3) * 2;
    __half* orow_hi = o + (bL + grow_hi) * DMODEL + h * HDIM + (lane & 3) * 2;
#pragma unroll
    for (int n = 0; n < 8; n++) {
        *(__half2*)(orow_lo + n * 8) = __floats2half2_rn(oa[n][0] * inv_lo, oa[n][1] * inv_lo);
        *(__half2*)(orow_hi + n * 8) = __floats2half2_rn(oa[n][2] * inv_hi, oa[n][3] * inv_hi);
    }
}

// ---------------- launcher ----------------
extern "C" void kernel_launch(void* const* d_in, const int* in_sizes, int n_in,
                              void* d_out, int out_size)
{
    const float* x     = (const float*)d_in[0];
    const float* w_qkv = (const float*)d_in[1];
    const float* b_qkv = (const float*)d_in[2];
    const float* w_out = (const float*)d_in[3];
    const float* b_out = (const float*)d_in[4];
    const float* w_fc1 = (const float*)d_in[5];
    const float* b_fc1 = (const float*)d_in[6];
    const float* w_fc2 = (const float*)d_in[7];
    const float* b_fc2 = (const float*)d_in[8];
    const float* ln1_g = (const float*)d_in[9];
    const float* ln1_b = (const float*)d_in[10];
    const float* ln2_g = (const float*)d_in[11];
    const float* ln2_b = (const float*)d_in[12];
    float* out = (float*)d_out;

    __half *h, *qkv, *o, *x1h, *fc1, *wT;
    cudaGetSymbolAddress((void**)&h,   g_hh);
    cudaGetSymbolAddress((void**)&qkv, g_qkvh);
    cudaGetSymbolAddress((void**)&o,   g_oh);
    cudaGetSymbolAddress((void**)&x1h, g_x1h);
    cudaGetSymbolAddress((void**)&fc1, g_fc1h);
    cudaGetSymbolAddress((void**)&wT,  g_wTh);

    __half* wqkvT = wT;
    __half* woutT = wqkvT + 3072 * 1024;
    __half* wfc1T = woutT + 1024 * 1024;
    __half* wfc2T = wfc1T + 4096 * 1024;

    cudaFuncSetAttribute((const void*)hgemm_tc<0, __half, float>,  cudaFuncAttributeMaxDynamicSharedMemorySize, GEMM_SMEM);
    cudaFuncSetAttribute((const void*)hgemm_tc<1, __half, float>,  cudaFuncAttributeMaxDynamicSharedMemorySize, GEMM_SMEM);
    cudaFuncSetAttribute((const void*)hgemm_tc<2, __half, float>,  cudaFuncAttributeMaxDynamicSharedMemorySize, GEMM_SMEM);
    cudaFuncSetAttribute((const void*)hgemm_tc<1, float, __half>,  cudaFuncAttributeMaxDynamicSharedMemorySize, GEMM_SMEM);
    cudaFuncSetAttribute(attn_h_kernel, cudaFuncAttributeMaxDynamicSharedMemorySize, ATT_SMEM);

    // 0) transpose all weights in one launch
    transpose4_kernel<<<TP_N3, 256>>>(w_qkv, wqkvT, w_out, woutT,
                                      w_fc1, wfc1T, w_fc2, wfc2T);

    // 1) LN1
    ln_kernel<float><<<MROWS, 256>>>(x, ln1_g, ln1_b, h);

    // 2) QKV projection
    hgemm_tc<0, __half, float><<<dim3(D3 / 128, MROWS / 128), 128, GEMM_SMEM>>>(
        h, wqkvT, b_qkv, nullptr, qkv, MROWS, D3, DMODEL);

    // 3) causal attention (64-row q-tiles)
    attn_h_kernel<<<dim3(SEQ / 64, BATCH * NHEAD), 128, ATT_SMEM>>>(qkv, o);

    // 4) out projection + residual -> x1 (fp16)
    hgemm_tc<1, __half, float><<<dim3(DMODEL / 128, MROWS / 128), 128, GEMM_SMEM>>>(
        o, woutT, b_out, x, x1h, MROWS, DMODEL, DMODEL);

    // 5) LN2
    ln_kernel<__half><<<MROWS, 256>>>(x1h, ln2_g, ln2_b, h);

    // 6) FC1 + exact GELU
    hgemm_tc<2, __half, float><<<dim3(INNER / 128, MROWS / 128), 128, GEMM_SMEM>>>(
        h, wfc1T, b_fc1, nullptr, fc1, MROWS, INNER, DMODEL);

    // 7) FC2 + residual -> out (fp32)
    hgemm_tc<1, float, __half><<<dim3(DMODEL / 128, MROWS / 128), 128, GEMM_SMEM>>>(
        fc1, wfc2T, b_fc2, x1h, out, MROWS, DMODEL, INNER);
}

// round 17
// speedup vs baseline: 1.0381x; 1.0031x over previous
#include <cuda_runtime.h>
#include <cuda_fp16.h>
#include <cuda_bf16.h>
#include <math.h>
#include <cstdint>

// Problem constants
#define BATCH 2
#define SEQ   2048
#define MROWS (BATCH*SEQ)       // 4096
#define DMODEL 1024
#define D3    (3*DMODEL)        // 3072
#define INNER (4*DMODEL)        // 4096
#define NHEAD 16
#define HDIM  64

// ---------------- scratch (device globals; no allocations allowed) ----------
__device__ __half g_hh  [MROWS*DMODEL];   // LN output (fp16)
__device__ __half g_qkvh[MROWS*D3];       // QKV projection (fp16)
__device__ __half g_oh  [MROWS*DMODEL];   // attention output (fp16)
__device__ __half g_x1h [MROWS*DMODEL];   // residual after attention (fp16)
__device__ __half g_fc1h[MROWS*INNER];    // FC1+GELU output (fp16)
__device__ __half g_wTh [12*1024*1024];   // transposed fp16 weights

// ---------------- helpers ----------------
__device__ __forceinline__ uint32_t smem_u32(const void* p) {
    uint32_t a;
    asm("{ .reg .u64 t; cvta.to.shared.u64 t, %1; cvt.u32.u64 %0, t; }" : "=r"(a) : "l"(p));
    return a;
}
#define SW64(x)  ((x) ^ (((x) >> 3) & 0x30))
#define SW128(x) ((x) ^ (((x) >> 3) & 0x70))
#define CP16(sa, ga) \
    asm volatile("cp.async.cg.shared.global [%0], [%1], 16;" :: "r"(sa), "l"(ga) : "memory")

__device__ __forceinline__ void ldsm4(uint32_t* r, uint32_t a) {
    asm volatile("ldmatrix.sync.aligned.m8n8.x4.shared.b16 {%0,%1,%2,%3}, [%4];"
        : "=r"(r[0]), "=r"(r[1]), "=r"(r[2]), "=r"(r[3]) : "r"(a));
}
__device__ __forceinline__ void ldsm4t(uint32_t* r, uint32_t a) {
    asm volatile("ldmatrix.sync.aligned.m8n8.x4.trans.shared.b16 {%0,%1,%2,%3}, [%4];"
        : "=r"(r[0]), "=r"(r[1]), "=r"(r[2]), "=r"(r[3]) : "r"(a));
}
__device__ __forceinline__ void mma16(float* d, const uint32_t* a, const uint32_t* b) {
    asm volatile("mma.sync.aligned.m16n8k16.row.col.f32.f16.f16.f32 "
        "{%0,%1,%2,%3}, {%4,%5,%6,%7}, {%8,%9}, {%0,%1,%2,%3};"
        : "+f"(d[0]), "+f"(d[1]), "+f"(d[2]), "+f"(d[3])
        : "r"(a[0]), "r"(a[1]), "r"(a[2]), "r"(a[3]), "r"(b[0]), "r"(b[1]));
}

// ---------------- batched transpose to fp16 (one launch, 4 matrices) --------
#define TP_N0 3072
#define TP_N1 4096
#define TP_N2 8192
#define TP_N3 12288

__global__ __launch_bounds__(256) void transpose4_kernel(
    const float* __restrict__ s0, __half* __restrict__ d0,
    const float* __restrict__ s1, __half* __restrict__ d1,
    const float* __restrict__ s2, __half* __restrict__ d2,
    const float* __restrict__ s3, __half* __restrict__ d3)
{
    const int bid = blockIdx.x;
    const float* src; __half* dst; int R, C, bx, by;
    if (bid < TP_N0)      { src = s0; dst = d0; R = DMODEL; C = D3;
                            const int l = bid;          bx = l % 96;  by = l / 96;  }
    else if (bid < TP_N1) { src = s1; dst = d1; R = DMODEL; C = DMODEL;
                            const int l = bid - TP_N0;  bx = l % 32;  by = l / 32;  }
    else if (bid < TP_N2) { src = s2; dst = d2; R = DMODEL; C = INNER;
                            const int l = bid - TP_N1;  bx = l % 128; by = l / 128; }
    else                  { src = s3; dst = d3; R = INNER;  C = DMODEL;
                            const int l = bid - TP_N2;  bx = l % 32;  by = l / 32;  }

    __shared__ float tile[32][33];
    const int c0 = bx * 32, r0 = by * 32;
    const int tx = threadIdx.x & 31, ty = threadIdx.x >> 5;
#pragma unroll
    for (int i = 0; i < 4; i++)
        tile[ty + 8 * i][tx] = src[(size_t)(r0 + ty + 8 * i) * C + c0 + tx];
    __syncthreads();
#pragma unroll
    for (int i = 0; i < 4; i++)
        dst[(size_t)(c0 + ty + 8 * i) * R + r0 + tx] = __float2half(tile[tx][ty + 8 * i]);
}

// ---------------- fp16 tensor-core GEMM (locked optimum) --------------------
#define GS_ABYTES 8192
#define GS_STAGE  16384
#define GEMM_SMEM (4 * GS_STAGE)   // 65536

template<int EPI, typename CT, typename RT>
__global__ __launch_bounds__(128, 2) void hgemm_tc(
    const __half* __restrict__ A, const __half* __restrict__ Bt,
    const float* __restrict__ bias, const RT* __restrict__ res,
    CT* __restrict__ C, int M, int N, int K)
{
    extern __shared__ char smem[];
    const uint32_t sb = smem_u32(smem);
    const int tid = threadIdx.x, lane = tid & 31, wid = tid >> 5;
    const int warp_m = wid >> 1, warp_n = wid & 1;
    const int m0 = blockIdx.y * 128, n0 = blockIdx.x * 128;
    const int mb = warp_m * 64, nb = warp_n * 64;

    const int u = lane >> 3, ur = lane & 7;
    uint32_t aoff[4], boff[4];
#pragma unroll
    for (int i = 0; i < 4; i++)
        aoff[i] = (uint32_t)(mb + i * 16 + (u & 1) * 8 + ur) * 64 + (u >> 1) * 16;
#pragma unroll
    for (int p = 0; p < 4; p++)
        boff[p] = (uint32_t)(nb + p * 16 + (u >> 1) * 8 + ur) * 64 + (u & 1) * 16;

    float acc[4][8][4];
#pragma unroll
    for (int i = 0; i < 4; i++)
#pragma unroll
        for (int j = 0; j < 8; j++)
#pragma unroll
            for (int q = 0; q < 4; q++) acc[i][j][q] = 0.f;

    const int nk = K >> 5;

#define H_ISSUE(t)                                                             \
    do {                                                                       \
        const uint32_t sa_ = sb + ((t) & 3) * GS_STAGE;                        \
        const uint32_t sbB_ = sa_ + GS_ABYTES;                                 \
        _Pragma("unroll")                                                      \
        for (int i_ = 0; i_ < 4; i_++) {                                       \
            const int idx_ = tid + 128 * i_;                                   \
            const int r_ = idx_ >> 2, c_ = idx_ & 3;                           \
            const uint32_t so_ = SW64((uint32_t)r_ * 64 + c_ * 16);            \
            CP16(sa_ + so_, A + (size_t)(m0 + r_) * K + (t) * 32 + c_ * 8);    \
            CP16(sbB_ + so_, Bt + (size_t)(n0 + r_) * K + (t) * 32 + c_ * 8);  \
        }                                                                      \
        asm volatile("cp.async.commit_group;" ::: "memory");                   \
    } while (0)

    H_ISSUE(0); H_ISSUE(1); H_ISSUE(2);

    for (int t = 0; t < nk; t++) {
        const int rem = nk - 1 - t;
        if (rem >= 2)       asm volatile("cp.async.wait_group 2;" ::: "memory");
        else if (rem == 1)  asm volatile("cp.async.wait_group 1;" ::: "memory");
        else                asm volatile("cp.async.wait_group 0;" ::: "memory");
        __syncthreads();

        if (t + 3 < nk) H_ISSUE(t + 3);

        const uint32_t sa = sb + (t & 3) * GS_STAGE;
        const uint32_t sbB = sa + GS_ABYTES;
#pragma unroll
        for (int s = 0; s < 2; s++) {
            uint32_t af[4][4], bf[8][2];
#pragma unroll
            for (int i = 0; i < 4; i++)
                ldsm4(af[i], sa + SW64(aoff[i] + s * 32));
#pragma unroll
            for (int p = 0; p < 4; p++) {
                uint32_t r4[4];
                ldsm4(r4, sbB + SW64(boff[p] + s * 32));
                bf[2 * p][0] = r4[0]; bf[2 * p][1] = r4[1];
                bf[2 * p + 1][0] = r4[2]; bf[2 * p + 1][1] = r4[3];
            }
#pragma unroll
            for (int i = 0; i < 4; i++)
#pragma unroll
                for (int j = 0; j < 8; j++) mma16(acc[i][j], af[i], bf[j]);
        }
        __syncthreads();
    }
#undef H_ISSUE

    // ---- epilogue ----
    const int r0 = m0 + mb + (lane >> 2);
    const int c0 = n0 + nb + (lane & 3) * 2;
#pragma unroll
    for (int i = 0; i < 4; i++) {
#pragma unroll
        for (int j = 0; j < 8; j++) {
            const int col = c0 + j * 8;
            const float bx = bias[col], by = bias[col + 1];
#pragma unroll
            for (int hh = 0; hh < 2; hh++) {
                const int row = r0 + i * 16 + hh * 8;
                float vx = acc[i][j][hh * 2 + 0] + bx;
                float vy = acc[i][j][hh * 2 + 1] + by;
                if (EPI == 1) {
                    if (sizeof(RT) == 2) {
                        const __half2 rr = *(const __half2*)((const __half*)res + (size_t)row * N + col);
                        const float2 rf = __half22float2(rr);
                        vx += rf.x; vy += rf.y;
                    } else {
                        const float2 rr = *(const float2*)((const float*)res + (size_t)row * N + col);
                        vx += rr.x; vy += rr.y;
                    }
                }
                if (EPI == 2) {
                    vx = 0.5f * vx * (1.f + erff(vx * 0.70710678118654752f));
                    vy = 0.5f * vy * (1.f + erff(vy * 0.70710678118654752f));
                }
                CT* cp = C + (size_t)row * N + col;
                if (sizeof(CT) == 2) {
                    *(__half2*)cp = __floats2half2_rn(vx, vy);
                } else {
                    float2 v; v.x = vx; v.y = vy;
                    *(float2*)cp = v;
                }
            }
        }
    }
}

// ---------------- LayerNorm (templated input, fp16 output) ------------------
template<typename IT>
__global__ __launch_bounds__(256) void ln_kernel(
    const IT* __restrict__ x, const float* __restrict__ g,
    const float* __restrict__ b, __half* __restrict__ out)
{
    __shared__ float red[16];
    const size_t row = blockIdx.x;
    const int tid = threadIdx.x;

    float4 v;
    if (sizeof(IT) == 2) {
        const uint2 pk = ((const uint2*)((const __half*)x + row * DMODEL))[tid];
        const float2 a = __half22float2(*(const __half2*)&pk.x);
        const float2 c = __half22float2(*(const __half2*)&pk.y);
        v.x = a.x; v.y = a.y; v.z = c.x; v.w = c.y;
    } else {
        v = ((const float4*)((const float*)x + row * DMODEL))[tid];
    }
    float s1 = v.x + v.y + v.z + v.w;
    float s2 = v.x * v.x + v.y * v.y + v.z * v.z + v.w * v.w;
#pragma unroll
    for (int o = 16; o; o >>= 1) {
        s1 += __shfl_xor_sync(0xffffffffu, s1, o);
        s2 += __shfl_xor_sync(0xffffffffu, s2, o);
    }
    if ((tid & 31) == 0) { red[tid >> 5] = s1; red[8 + (tid >> 5)] = s2; }
    __syncthreads();
    if (tid < 32) {
        float a = (tid < 8) ? red[tid] : 0.f;
        float c = (tid < 8) ? red[8 + tid] : 0.f;
#pragma unroll
        for (int o = 4; o; o >>= 1) {
            a += __shfl_xor_sync(0xffffffffu, a, o);
            c += __shfl_xor_sync(0xffffffffu, c, o);
        }
        if (tid == 0) { red[0] = a; red[8] = c; }
    }
    __syncthreads();
    const float mu  = red[0] * (1.f / DMODEL);
    const float var = red[8] * (1.f / DMODEL) - mu * mu;
    const float r   = rsqrtf(var + 1e-5f);

    const float4 gg = ((const float4*)g)[tid];
    const float4 bb = ((const float4*)b)[tid];
    __half2 h01 = __floats2half2_rn((v.x - mu) * r * gg.x + bb.x,
                                    (v.y - mu) * r * gg.y + bb.y);
    __half2 h23 = __floats2half2_rn((v.z - mu) * r * gg.z + bb.z,
                                    (v.w - mu) * r * gg.w + bb.w);
    uint2 pk;
    pk.x = *(uint32_t*)&h01;
    pk.y = *(uint32_t*)&h23;
    *(uint2*)(out + row * DMODEL + tid * 4) = pk;
}

// ---------------- fp16 flash attention (64-row tiles, 4 warps, 2-stage) -----
// Smem: Q/P [64][64]h = 8KB + 2 stages of (K 8KB + V 8KB) = 40KB total.
// __launch_bounds__(128, 4): regs capped at 128 -> 4 CTAs/SM.
#define AT_KV_STAGE 16384
#define ATT_SMEM (8192 + 2 * AT_KV_STAGE)   // 40960

__global__ __launch_bounds__(128, 4) void attn_h_kernel(
    const __half* __restrict__ qkv, __half* __restrict__ o)
{
    extern __shared__ char sm[];
    const uint32_t uQ = smem_u32(sm);
    const uint32_t uKV = uQ + 8192;

    const int tid = threadIdx.x, lane = tid & 31, w = tid >> 5;   // w: 0..3
    const int bh = blockIdx.y;
    const int b = bh >> 4, h = bh & 15;
    const int qb = (int)gridDim.x - 1 - (int)blockIdx.x;   // heavy tiles first
    const int q0 = qb * 64;
    const size_t bL = (size_t)b * SEQ;

    const int u = lane >> 3, ur = lane & 7;
    const uint32_t aoff = (uint32_t)(w * 16 + (u & 1) * 8 + ur) * 128 + (u >> 1) * 16;
    uint32_t boffK[4];
#pragma unroll
    for (int p = 0; p < 4; p++)
        boffK[p] = (uint32_t)(p * 16 + (u >> 1) * 8 + ur) * 128 + (u & 1) * 16;
    uint32_t boffV[4];
#pragma unroll
    for (int p = 0; p < 4; p++)
        boffV[p] = (uint32_t)((u & 1) * 8 + ur) * 128 + p * 32 + (u >> 1) * 16;

    // K/V for block kb -> stage kb&1 (128 threads: 4 iters x 2 CP16)
#define A_ISSUE(kb)                                                            \
    do {                                                                       \
        const uint32_t uS_ = uKV + ((kb) & 1) * AT_KV_STAGE;                   \
        _Pragma("unroll")                                                      \
        for (int i_ = 0; i_ < 4; i_++) {                                       \
            const int idx_ = tid + 128 * i_;                                   \
            const int r_ = idx_ >> 3, c_ = idx_ & 7;                           \
            const uint32_t so_ = SW128((uint32_t)r_ * 128 + c_ * 16);          \
            const __half* kp_ = qkv + (bL + (kb) * 64 + r_) * D3 + DMODEL      \
                                + h * HDIM + c_ * 8;                           \
            CP16(uS_ + so_, kp_);                                              \
            CP16(uS_ + 8192 + so_, kp_ + DMODEL);                              \
        }                                                                      \
        asm volatile("cp.async.commit_group;" ::: "memory");                   \
    } while (0)

    const int nkb = qb + 1;

    // ---- prologue: K/V block 0, then Q tile ----
    A_ISSUE(0);
    {
#pragma unroll
        for (int i = 0; i < 4; i++) {
            const int idx = tid + 128 * i;
            const int r = idx >> 3, c = idx & 7;
            CP16(uQ + SW128((uint32_t)r * 128 + c * 16),
                 qkv + (bL + q0 + r) * D3 + h * HDIM + c * 8);
        }
        asm volatile("cp.async.commit_group;" ::: "memory");
    }
    asm volatile("cp.async.wait_group 0;" ::: "memory");
    __syncthreads();

    uint32_t qf[4][4];
#pragma unroll
    for (int s = 0; s < 4; s++) ldsm4(qf[s], uQ + SW128(aoff + s * 32));

    float oa[8][4];
#pragma unroll
    for (int n = 0; n < 8; n++)
#pragma unroll
        for (int q = 0; q < 4; q++) oa[n][q] = 0.f;
    float m_lo = -1e30f, m_hi = -1e30f, l_lo = 0.f, l_hi = 0.f;

    const int grow_lo = q0 + w * 16 + (lane >> 2);
    const int grow_hi = grow_lo + 8;

    for (int kb = 0; kb < nkb; kb++) {
        // prefetch next K/V block into the other stage
        if (kb + 1 < nkb) {
            A_ISSUE(kb + 1);
            asm volatile("cp.async.wait_group 1;" ::: "memory");
        } else {
            asm volatile("cp.async.wait_group 0;" ::: "memory");
        }
        __syncthreads();

        const uint32_t uK = uKV + (kb & 1) * AT_KV_STAGE;
        const uint32_t uV = uK + 8192;

        float sc[8][4];
#pragma unroll
        for (int n = 0; n < 8; n++)
#pragma unroll
            for (int q = 0; q < 4; q++) sc[n][q] = 0.f;
#pragma unroll
        for (int s = 0; s < 4; s++) {
            uint32_t bf[8][2];
#pragma unroll
            for (int p = 0; p < 4; p++) {
                uint32_t r4[4];
                ldsm4(r4, uK + SW128(boffK[p] + s * 32));
                bf[2 * p][0] = r4[0]; bf[2 * p][1] = r4[1];
                bf[2 * p + 1][0] = r4[2]; bf[2 * p + 1][1] = r4[3];
            }
#pragma unroll
            for (int n = 0; n < 8; n++) mma16(sc[n], qf[s], bf[n]);
        }

        const bool need_mask = (kb == qb);
        const int c0g = kb * 64 + (lane & 3) * 2;
#pragma unroll
        for (int n = 0; n < 8; n++) {
            const int col0 = c0g + n * 8, col1 = col0 + 1;
            float s0 = sc[n][0] * 0.125f, s1 = sc[n][1] * 0.125f;
            float s2 = sc[n][2] * 0.125f, s3 = sc[n][3] * 0.125f;
            if (need_mask) {
                if (col0 > grow_lo) s0 = -1e30f;
                if (col1 > grow_lo) s1 = -1e30f;
                if (col0 > grow_hi) s2 = -1e30f;
                if (col1 > grow_hi) s3 = -1e30f;
            }
            sc[n][0] = s0; sc[n][1] = s1; sc[n][2] = s2; sc[n][3] = s3;
        }

        float bm_lo = -1e30f, bm_hi = -1e30f;
#pragma unroll
        for (int n = 0; n < 8; n++) {
            bm_lo = fmaxf(bm_lo, fmaxf(sc[n][0], sc[n][1]));
            bm_hi = fmaxf(bm_hi, fmaxf(sc[n][2], sc[n][3]));
        }
        bm_lo = fmaxf(bm_lo, __shfl_xor_sync(0xffffffffu, bm_lo, 1));
        bm_lo = fmaxf(bm_lo, __shfl_xor_sync(0xffffffffu, bm_lo, 2));
        bm_hi = fmaxf(bm_hi, __shfl_xor_sync(0xffffffffu, bm_hi, 1));
        bm_hi = fmaxf(bm_hi, __shfl_xor_sync(0xffffffffu, bm_hi, 2));
        const float mn_lo = fmaxf(m_lo, bm_lo);
        const float mn_hi = fmaxf(m_hi, bm_hi);
        const float f_lo = __expf(m_lo - mn_lo);
        const float f_hi = __expf(m_hi - mn_hi);
        m_lo = mn_lo; m_hi = mn_hi;

        float ps_lo = 0.f, ps_hi = 0.f;
#pragma unroll
        for (int n = 0; n < 8; n++) {
            sc[n][0] = __expf(sc[n][0] - mn_lo);
            sc[n][1] = __expf(sc[n][1] - mn_lo);
            sc[n][2] = __expf(sc[n][2] - mn_hi);
            sc[n][3] = __expf(sc[n][3] - mn_hi);
            ps_lo += sc[n][0] + sc[n][1];
            ps_hi += sc[n][2] + sc[n][3];
        }
        ps_lo += __shfl_xor_sync(0xffffffffu, ps_lo, 1);
        ps_lo += __shfl_xor_sync(0xffffffffu, ps_lo, 2);
        ps_hi += __shfl_xor_sync(0xffffffffu, ps_hi, 1);
        ps_hi += __shfl_xor_sync(0xffffffffu, ps_hi, 2);
        l_lo = l_lo * f_lo + ps_lo;
        l_hi = l_hi * f_hi + ps_hi;

#pragma unroll
        for (int n = 0; n < 8; n++) {
            oa[n][0] *= f_lo; oa[n][1] *= f_lo;
            oa[n][2] *= f_hi; oa[n][3] *= f_hi;
        }

        // ---- write P (fp16) into Q region (warp-private rows) ----
        {
            const uint32_t plo = (uint32_t)(w * 16 + (lane >> 2)) * 128 + (lane & 3) * 4;
            const uint32_t phi = plo + 8 * 128;
#pragma unroll
            for (int n = 0; n < 8; n++) {
                *(__half2*)(sm + SW128(plo + n * 16)) = __floats2half2_rn(sc[n][0], sc[n][1]);
                *(__half2*)(sm + SW128(phi + n * 16)) = __floats2half2_rn(sc[n][2], sc[n][3]);
            }
        }
        __syncwarp();

        // ---- O += P @ V ----
#pragma unroll
        for (int s = 0; s < 4; s++) {
            uint32_t ap[4];
            ldsm4(ap, uQ + SW128(aoff + s * 32));
#pragma unroll
            for (int p = 0; p < 4; p++) {
                uint32_t r4[4];
                ldsm4t(r4, uV + SW128(boffV[p] + s * 16 * 128));
                uint32_t b0[2] = { r4[0], r4[1] };
                uint32_t b1[2] = { r4[2], r4[3] };
                mma16(oa[2 * p], ap, b0);
                mma16(oa[2 * p + 1], ap, b1);
            }
        }
        __syncthreads();   // reads of stage (kb&1) done before overwrite at kb+2
    }
#undef A_ISSUE

    const float inv_lo = 1.f / l_lo, inv_hi = 1.f / l_hi;
    __half* orow_lo = o + (bL + grow_lo) * DMODEL + h * HDIM + (lane & 3) * 2;
    __half* orow_hi = o + (bL + grow_hi) * DMODEL + h * HDIM + (lane & 3) * 2;
#pragma unroll
    for (int n = 0; n < 8; n++) {
        *(__half2*)(orow_lo + n * 8) = __floats2half2_rn(oa[n][0] * inv_lo, oa[n][1] * inv_lo);
        *(__half2*)(orow_hi + n * 8) = __floats2half2_rn(oa[n][2] * inv_hi, oa[n][3] * inv_hi);
    }
}

// ---------------- launcher ----------------
extern "C" void kernel_launch(void* const* d_in, const int* in_sizes, int n_in,
                              void* d_out, int out_size)
{
    const float* x     = (const float*)d_in[0];
    const float* w_qkv = (const float*)d_in[1];
    const float* b_qkv = (const float*)d_in[2];
    const float* w_out = (const float*)d_in[3];
    const float* b_out = (const float*)d_in[4];
    const float* w_fc1 = (const float*)d_in[5];
    const float* b_fc1 = (const float*)d_in[6];
    const float* w_fc2 = (const float*)d_in[7];
    const float* b_fc2 = (const float*)d_in[8];
    const float* ln1_g = (const float*)d_in[9];
    const float* ln1_b = (const float*)d_in[10];
    const float* ln2_g = (const float*)d_in[11];
    const float* ln2_b = (const float*)d_in[12];
    float* out = (float*)d_out;

    __half *h, *qkv, *o, *x1h, *fc1, *wT;
    cudaGetSymbolAddress((void**)&h,   g_hh);
    cudaGetSymbolAddress((void**)&qkv, g_qkvh);
    cudaGetSymbolAddress((void**)&o,   g_oh);
    cudaGetSymbolAddress((void**)&x1h, g_x1h);
    cudaGetSymbolAddress((void**)&fc1, g_fc1h);
    cudaGetSymbolAddress((void**)&wT,  g_wTh);

    __half* wqkvT = wT;
    __half* woutT = wqkvT + 3072 * 1024;
    __half* wfc1T = woutT + 1024 * 1024;
    __half* wfc2T = wfc1T + 4096 * 1024;

    cudaFuncSetAttribute((const void*)hgemm_tc<0, __half, float>,  cudaFuncAttributeMaxDynamicSharedMemorySize, GEMM_SMEM);
    cudaFuncSetAttribute((const void*)hgemm_tc<1, __half, float>,  cudaFuncAttributeMaxDynamicSharedMemorySize, GEMM_SMEM);
    cudaFuncSetAttribute((const void*)hgemm_tc<2, __half, float>,  cudaFuncAttributeMaxDynamicSharedMemorySize, GEMM_SMEM);
    cudaFuncSetAttribute((const void*)hgemm_tc<1, float, __half>,  cudaFuncAttributeMaxDynamicSharedMemorySize, GEMM_SMEM);
    cudaFuncSetAttribute(attn_h_kernel, cudaFuncAttributeMaxDynamicSharedMemorySize, ATT_SMEM);

    // 0) transpose all weights in one launch
    transpose4_kernel<<<TP_N3, 256>>>(w_qkv, wqkvT, w_out, woutT,
                                      w_fc1, wfc1T, w_fc2, wfc2T);

    // 1) LN1
    ln_kernel<float><<<MROWS, 256>>>(x, ln1_g, ln1_b, h);

    // 2) QKV projection
    hgemm_tc<0, __half, float><<<dim3(D3 / 128, MROWS / 128), 128, GEMM_SMEM>>>(
        h, wqkvT, b_qkv, nullptr, qkv, MROWS, D3, DMODEL);

    // 3) causal attention (64-row q-tiles, 4 CTAs/SM)
    attn_h_kernel<<<dim3(SEQ / 64, BATCH * NHEAD), 128, ATT_SMEM>>>(qkv, o);

    // 4) out projection + residual -> x1 (fp16)
    hgemm_tc<1, __half, float><<<dim3(DMODEL / 128, MROWS / 128), 128, GEMM_SMEM>>>(
        o, woutT, b_out, x, x1h, MROWS, DMODEL, DMODEL);

    // 5) LN2
    ln_kernel<__half><<<MROWS, 256>>>(x1h, ln2_g, ln2_b, h);

    // 6) FC1 + exact GELU
    hgemm_tc<2, __half, float><<<dim3(INNER / 128, MROWS / 128), 128, GEMM_SMEM>>>(
        h, wfc1T, b_fc1, nullptr, fc1, MROWS, INNER, DMODEL);

    // 7) FC2 + residual -> out (fp32)
    hgemm_tc<1, float, __half><<<dim3(DMODEL / 128, MROWS / 128), 128, GEMM_SMEM>>>(
        fc1, wfc2T, b_fc2, x1h, out, MROWS, DMODEL, INNER);
}